// round 6
// baseline (speedup 1.0000x reference)
#include <cuda_runtime.h>
#include <cuda_bf16.h>
#include <math.h>
#include <cstdint>

#define B_   2
#define T_   2048
#define DM   2048
#define NH   16
#define HD   128
#define HP_  8
#define QKV_N 6144
#define LAMBDA_INIT  0.7008206670670481f
#define ONE_MINUS_LI 0.2991793329329519f

// ---------------- scratch ----------------
__device__ float g_qkv[(size_t)B_ * T_ * QKV_N];
__device__ float g_gate[(size_t)B_ * T_ * DM];
__device__ float g_Q[(size_t)B_ * NH * T_ * HD];
__device__ float g_K[(size_t)B_ * NH * T_ * HD];
__device__ float g_V[(size_t)B_ * HP_ * T_ * 256];
__device__ float g_Vt[(size_t)B_ * HP_ * 256 * T_];
__device__ float g_Y[(size_t)B_ * NH * T_ * 256];
__device__ float g_lam[HP_];
__device__ __nv_bfloat16 g_Xhi[(size_t)B_ * T_ * DM];
__device__ __nv_bfloat16 g_Xlo[(size_t)B_ * T_ * DM];
__device__ __nv_bfloat16 g_WqHiT[(size_t)QKV_N * DM];
__device__ __nv_bfloat16 g_WqLoT[(size_t)QKV_N * DM];
__device__ __nv_bfloat16 g_WgHiT[(size_t)DM * DM];
__device__ __nv_bfloat16 g_WgLoT[(size_t)DM * DM];

// ================= helpers =================
__device__ __forceinline__ uint32_t smem_u32(const void* p) {
    uint32_t a;
    asm("{ .reg .u64 t; cvta.to.shared.u64 t, %1; cvt.u32.u64 %0, t; }" : "=r"(a) : "l"(p));
    return a;
}
#define CP_ASYNC16(dst, src) \
    asm volatile("cp.async.cg.shared.global [%0], [%1], 16;" :: "r"(dst), "l"(src) : "memory")
#define CP_COMMIT() asm volatile("cp.async.commit_group;" ::: "memory")
#define CP_WAIT0()  asm volatile("cp.async.wait_group 0;" ::: "memory")
#define CP_WAIT1()  asm volatile("cp.async.wait_group 1;" ::: "memory")
#define CP_WAIT2()  asm volatile("cp.async.wait_group 2;" ::: "memory")
#define CVT_TF32(d, s) asm("cvt.rna.tf32.f32 %0, %1;" : "=f"(d) : "f"(s))
#define EX2F(d, s)     asm("ex2.approx.f32 %0, %1;" : "=f"(d) : "f"(s))
#define LDMX4(r, addr) \
    asm volatile("ldmatrix.sync.aligned.m8n8.x4.shared.b16 {%0,%1,%2,%3}, [%4];" \
        : "=r"((r)[0]), "=r"((r)[1]), "=r"((r)[2]), "=r"((r)[3]) : "r"(addr))

__device__ __forceinline__ void mma_tf32(float* c, const uint32_t* a, uint32_t b0, uint32_t b1) {
    asm volatile(
        "mma.sync.aligned.m16n8k8.row.col.f32.tf32.tf32.f32 "
        "{%0,%1,%2,%3}, {%4,%5,%6,%7}, {%8,%9}, {%0,%1,%2,%3};"
        : "+f"(c[0]), "+f"(c[1]), "+f"(c[2]), "+f"(c[3])
        : "r"(a[0]), "r"(a[1]), "r"(a[2]), "r"(a[3]), "r"(b0), "r"(b1));
}
__device__ __forceinline__ void mma_bf16(float* c, const uint32_t* a, uint32_t b0, uint32_t b1) {
    asm volatile(
        "mma.sync.aligned.m16n8k16.row.col.f32.bf16.bf16.f32 "
        "{%0,%1,%2,%3}, {%4,%5,%6,%7}, {%8,%9}, {%0,%1,%2,%3};"
        : "+f"(c[0]), "+f"(c[1]), "+f"(c[2]), "+f"(c[3])
        : "r"(a[0]), "r"(a[1]), "r"(a[2]), "r"(a[3]), "r"(b0), "r"(b1));
}

// ================= bf16 double-double GEMM: C = (Ahi+Alo) @ (Bhi+Blo)^T =================
// A: [M][K] bf16 pair; B: [N][K] bf16 pair (transposed weights). CTA 128x128, k16/stage.
#define NST 3
#define GBM 128
#define GBN 128
#define APB 48                       // smem row pitch bytes (16 bf16 used, pad to 48B)
#define A_SB (128 * APB)             // 6144 B per split
#define STAGE_B (4 * A_SB)           // Ahi,Alo,Bhi,Blo = 24576 B
#define GEMM_SMEM (NST * STAGE_B)    // 73728 B

__device__ __forceinline__ void gemm_stage_load(const __nv_bfloat16* __restrict__ Ahi,
                                                const __nv_bfloat16* __restrict__ Alo,
                                                const __nv_bfloat16* __restrict__ Bhi,
                                                const __nv_bfloat16* __restrict__ Blo,
                                                int K, int m0, int n0, int kt,
                                                uint32_t sbase, int tid) {
    int r = tid >> 1, c = tid & 1;
    uint32_t off = (uint32_t)(r * APB + c * 16);
    size_t ga = (size_t)(m0 + r) * K + kt * 16 + c * 8;
    size_t gb = (size_t)(n0 + r) * K + kt * 16 + c * 8;
    CP_ASYNC16(sbase + off,              Ahi + ga);
    CP_ASYNC16(sbase + A_SB + off,       Alo + ga);
    CP_ASYNC16(sbase + 2 * A_SB + off,   Bhi + gb);
    CP_ASYNC16(sbase + 3 * A_SB + off,   Blo + gb);
    CP_COMMIT();
}

__global__ void __launch_bounds__(256, 2) gemm_bf16_kernel(const __nv_bfloat16* __restrict__ Ahi,
                                                           const __nv_bfloat16* __restrict__ Alo,
                                                           const __nv_bfloat16* __restrict__ Bhi,
                                                           const __nv_bfloat16* __restrict__ Blo,
                                                           float* __restrict__ C,
                                                           int N, int K) {
    extern __shared__ char smraw[];
    uint32_t sm_b = smem_u32(smraw);
    const int tid = threadIdx.x;
    const int wid = tid >> 5;
    const int lane = tid & 31;
    const int warpM = wid & 1;
    const int warpN = wid >> 1;
    const int m0 = blockIdx.y * GBM;
    const int n0 = blockIdx.x * GBN;
    const int NT = K / 16;
    const int lr = lane >> 2;
    const int lc = lane & 3;
    const int lm_row = lane & 15;
    const int lm_hi  = (lane >> 4) * 16;

    float acc[4][4][4];
#pragma unroll
    for (int i = 0; i < 4; i++)
#pragma unroll
        for (int j = 0; j < 4; j++)
#pragma unroll
            for (int u = 0; u < 4; u++) acc[i][j][u] = 0.0f;

#pragma unroll
    for (int s = 0; s < NST - 1; s++)
        gemm_stage_load(Ahi, Alo, Bhi, Blo, K, m0, n0, s, sm_b + (uint32_t)(s * STAGE_B), tid);

    for (int kt = 0; kt < NT; kt++) {
        CP_WAIT1();
        __syncthreads();
        int nxt = kt + NST - 1;
        if (nxt < NT)
            gemm_stage_load(Ahi, Alo, Bhi, Blo, K, m0, n0, nxt,
                            sm_b + (uint32_t)((nxt % NST) * STAGE_B), tid);

        uint32_t sA = sm_b + (uint32_t)((kt % NST) * STAGE_B);
        uint32_t a_base = sA + (uint32_t)((warpM * 64 + lm_row) * APB + lm_hi);
        uint32_t b_base = sA + 2u * A_SB + (uint32_t)((warpN * 32 + lm_row) * APB + lm_hi);

        uint32_t bh[2][4], bl[2][4];
#pragma unroll
        for (int nb = 0; nb < 2; nb++) {
            LDMX4(bh[nb], b_base + (uint32_t)(nb * 16 * APB));
            LDMX4(bl[nb], b_base + (uint32_t)(nb * 16 * APB) + A_SB);
        }
#pragma unroll
        for (int ma = 0; ma < 4; ma++) {
            uint32_t ah[4], al[4];
            uint32_t addr = a_base + (uint32_t)(ma * 16 * APB);
            LDMX4(ah, addr);
            LDMX4(al, addr + A_SB);
#pragma unroll
            for (int na = 0; na < 4; na++) {
                int nb = na >> 1, j = na & 1;
                mma_bf16(acc[ma][na], ah, bh[nb][j], bh[nb][j + 2]);
                mma_bf16(acc[ma][na], ah, bl[nb][j], bl[nb][j + 2]);
                mma_bf16(acc[ma][na], al, bh[nb][j], bh[nb][j + 2]);
            }
        }
    }

#pragma unroll
    for (int ma = 0; ma < 4; ma++) {
        int r0 = m0 + warpM * 64 + ma * 16 + lr;
#pragma unroll
        for (int na = 0; na < 4; na++) {
            int c0 = n0 + warpN * 32 + na * 8 + lc * 2;
            *(float2*)(C + (size_t)r0 * N + c0)       = make_float2(acc[ma][na][0], acc[ma][na][1]);
            *(float2*)(C + (size_t)(r0 + 8) * N + c0) = make_float2(acc[ma][na][2], acc[ma][na][3]);
        }
    }
}

// ================= pre-kernels =================
__global__ void splitx_bf16_kernel(const float* __restrict__ x,
                                   __nv_bfloat16* __restrict__ xhi,
                                   __nv_bfloat16* __restrict__ xlo, int n4) {
    int i = blockIdx.x * blockDim.x + threadIdx.x;
    if (i < n4) {
        float4 v = ((const float4*)x)[i];
        float f[4] = {v.x, v.y, v.z, v.w};
        __nv_bfloat16 h[4], l[4];
#pragma unroll
        for (int j = 0; j < 4; j++) {
            h[j] = __float2bfloat16_rn(f[j]);
            l[j] = __float2bfloat16_rn(f[j] - __bfloat162float(h[j]));
        }
        ((uint2*)xhi)[i] = *(uint2*)h;
        ((uint2*)xlo)[i] = *(uint2*)l;
    }
}

// transpose + bf16-split: W[K][N] fp32 -> WhiT/WloT [N][K] bf16
__global__ void wsplit_t_kernel(const float* __restrict__ W,
                                __nv_bfloat16* __restrict__ WhiT,
                                __nv_bfloat16* __restrict__ WloT,
                                int K, int Nc) {
    __shared__ float tile[32][33];
    int n0 = blockIdx.x * 32, k0 = blockIdx.y * 32;
    int tx = threadIdx.x, ty = threadIdx.y;  // 32 x 8
#pragma unroll
    for (int i = 0; i < 4; i++)
        tile[ty + i * 8][tx] = W[(size_t)(k0 + ty + i * 8) * Nc + n0 + tx];
    __syncthreads();
#pragma unroll
    for (int i = 0; i < 4; i++) {
        float v = tile[tx][ty + i * 8];
        __nv_bfloat16 h = __float2bfloat16_rn(v);
        __nv_bfloat16 l = __float2bfloat16_rn(v - __bfloat162float(h));
        size_t o = (size_t)(n0 + ty + i * 8) * K + k0 + tx;
        WhiT[o] = h;
        WloT[o] = l;
    }
}

// ---------------- prep: rmsnorm(q,k) + RoPE ----------------
__global__ void prep_kernel() {
    int t = blockIdx.x, h = blockIdx.y, b = blockIdx.z;
    int d = threadIdx.x;
    const float* p = g_qkv + ((size_t)(b * T_ + t)) * QKV_N + h * 384;
    float qv = p[d], kv = p[128 + d], vv = p[256 + d];

    __shared__ float redq[4], redk[4];
    __shared__ float qs[128], ks[128];
    float q2 = qv * qv, k2 = kv * kv;
#pragma unroll
    for (int off = 16; off > 0; off >>= 1) {
        q2 += __shfl_xor_sync(0xffffffffu, q2, off);
        k2 += __shfl_xor_sync(0xffffffffu, k2, off);
    }
    if ((d & 31) == 0) { redq[d >> 5] = q2; redk[d >> 5] = k2; }
    __syncthreads();
    float sq = redq[0] + redq[1] + redq[2] + redq[3];
    float sk = redk[0] + redk[1] + redk[2] + redk[3];
    float qn = qv * rsqrtf(sq * (1.0f / 128.0f) + 1e-6f);
    float kn = kv * rsqrtf(sk * (1.0f / 128.0f) + 1e-6f);
    qs[d] = qn; ks[d] = kn;
    __syncthreads();

    int dd = d & 63;
    float freq = (float)t * expf(-(float)dd * (9.210340371976184f / 64.0f));
    float c = cosf(freq), s = sinf(freq);
    float qr, kr;
    if (d < 64) { qr =  qs[d] * c + qs[d + 64] * s;  kr =  ks[d] * c + ks[d + 64] * s; }
    else        { qr = -qs[dd] * s + qs[d] * c;      kr = -ks[dd] * s + ks[d] * c;     }

    const float QSCL = 0.08838834764831845f * 1.44269504088896340f;
    size_t qi = ((size_t)(b * NH + h) * T_ + t) * HD + d;
    g_Q[qi] = qr * QSCL;
    float krr; CVT_TF32(krr, kr);
    g_K[qi] = krr;
    float vvr; CVT_TF32(vvr, vv);
    size_t vi = ((size_t)(b * HP_ + (h >> 1)) * T_ + t) * 256 + (size_t)(h & 1) * 128 + d;
    g_V[vi] = vvr;
}

// ---------------- V transpose ----------------
__global__ void vtrans_kernel() {
    __shared__ float tile[32][33];
    int t0 = blockIdx.x * 32, e0 = blockIdx.y * 32, bhp = blockIdx.z;
    const float* src = g_V + (size_t)bhp * T_ * 256;
    float* dst = g_Vt + (size_t)bhp * 256 * T_;
    int tx = threadIdx.x, ty = threadIdx.y;
#pragma unroll
    for (int i = 0; i < 4; i++)
        tile[ty + i * 8][tx] = src[(size_t)(t0 + ty + i * 8) * 256 + e0 + tx];
    __syncthreads();
#pragma unroll
    for (int i = 0; i < 4; i++)
        dst[(size_t)(e0 + ty + i * 8) * T_ + t0 + tx] = tile[tx][ty + i * 8];
}

// ---------------- lambda ----------------
__global__ void lam_kernel(const float* __restrict__ lq1, const float* __restrict__ lk1,
                           const float* __restrict__ lq2, const float* __restrict__ lk2) {
    int hp = threadIdx.y;
    int lane = threadIdx.x;
    float s1 = lq1[hp*64 + lane] * lk1[hp*64 + lane] + lq1[hp*64 + lane + 32] * lk1[hp*64 + lane + 32];
    float s2 = lq2[hp*64 + lane] * lk2[hp*64 + lane] + lq2[hp*64 + lane + 32] * lk2[hp*64 + lane + 32];
#pragma unroll
    for (int off = 16; off > 0; off >>= 1) {
        s1 += __shfl_xor_sync(0xffffffffu, s1, off);
        s2 += __shfl_xor_sync(0xffffffffu, s2, off);
    }
    if (lane == 0) g_lam[hp] = expf(s1) - expf(s2) + LAMBDA_INIT;
}

// ---------------- flash attention, tf32 mma (unchanged from R5) ----------------
#define QP 132
#define KTP 132
#define VTP 76
#define PP 68
#define OFF_QHI 0
#define OFF_QLO (OFF_QHI + 64 * QP)
#define OFF_KS0 (OFF_QLO + 64 * QP)
#define OFF_KS1 (OFF_KS0 + 64 * KTP)
#define OFF_VT  (OFF_KS1 + 64 * KTP)
#define OFF_PS  (OFF_VT + 256 * VTP)
#define OFF_WMAX (OFF_PS + 64 * PP)
#define OFF_WSUM (OFF_WMAX + 128)
#define ATT_SMEM ((OFF_WSUM + 128) * 4)

__global__ void __launch_bounds__(256, 1) attn_kernel() {
    const int mt = gridDim.x - 1 - blockIdx.x;
    const int h = blockIdx.y, b = blockIdx.z;
    const int tid = threadIdx.x, wid = tid >> 5, lane = tid & 31;
    const int wM = wid & 3, wN = wid >> 2;
    const int lr = lane >> 2, lc = lane & 3;
    const int r0 = wM * 16 + lr;
    const int x_row = ((lane >> 3) & 1) * 8 + (lane & 7);
    const int x_col = (lane >> 4) * 4;

    extern __shared__ float sm[];
    uint32_t smb = smem_u32(sm);
    float* Ps = sm + OFF_PS;
    float* wmaxs = sm + OFF_WMAX;
    float* wsums = sm + OFF_WSUM;

    const float* Qg  = g_Q  + ((size_t)(b * NH + h) * T_ + (size_t)mt * 64) * HD;
    const float* Kg  = g_K  + (size_t)(b * NH + h) * T_ * HD;
    const float* Vtg = g_Vt + (size_t)(b * HP_ + (h >> 1)) * 256 * T_;
    float*       Yg  = g_Y  + (size_t)(b * NH + h) * T_ * 256;

#pragma unroll
    for (int i = 0; i < 8; i++) {
        int idx = tid + i * 256;
        int r = idx >> 5, c4 = (idx & 31) * 4;
        CP_ASYNC16(smb + (uint32_t)(OFF_KS0 + r * KTP + c4) * 4u,
                   Kg + (size_t)r * HD + c4);
    }
    CP_COMMIT();

    for (int c = tid; c < 64 * 32; c += 256) {
        int q = c >> 5, d4 = (c & 31) * 4;
        float4 v = *(const float4*)(Qg + (size_t)q * HD + d4);
        float f[4] = {v.x, v.y, v.z, v.w};
        float* hq = sm + OFF_QHI + q * QP + d4;
        float* lq = sm + OFF_QLO + q * QP + d4;
#pragma unroll
        for (int j = 0; j < 4; j++) {
            float hi; CVT_TF32(hi, f[j]);
            float lo = f[j] - hi;
            CVT_TF32(lo, lo);
            hq[j] = hi; lq[j] = lo;
        }
    }

    float O[16][4];
#pragma unroll
    for (int i = 0; i < 16; i++)
#pragma unroll
        for (int j = 0; j < 4; j++) O[i][j] = 0.0f;
    float m0 = -1e30f, m1 = -1e30f, l0 = 0.0f, l1 = 0.0f;

    const uint32_t qhi_base = smb + (uint32_t)(OFF_QHI + (wM * 16 + x_row) * QP + x_col) * 4u;
    const uint32_t qlo_base = qhi_base + (uint32_t)(64 * QP) * 4u;
    const uint32_t ps_base  = smb + (uint32_t)(OFF_PS + (wM * 16 + x_row) * PP + x_col) * 4u;
    const uint32_t vt_base  = smb + (uint32_t)(OFF_VT + (wN * 128 + x_row) * VTP + x_col) * 4u;
    const uint32_t ks_base0 = smb + (uint32_t)(OFF_KS0 + (wN * 32 + x_row) * KTP + x_col) * 4u;
    const uint32_t ks_base1 = smb + (uint32_t)(OFF_KS1 + (wN * 32 + x_row) * KTP + x_col) * 4u;

    for (int nt = 0; nt <= mt; nt++) {
        __syncthreads();
#pragma unroll
        for (int i = 0; i < 16; i++) {
            int idx = tid + i * 256;
            int r = idx >> 4, c4 = (idx & 15) * 4;
            CP_ASYNC16(smb + (uint32_t)(OFF_VT + r * VTP + c4) * 4u,
                       Vtg + (size_t)r * T_ + nt * 64 + c4);
        }
        CP_COMMIT();
        if (nt < mt) {
            int koff = ((nt + 1) & 1) ? OFF_KS1 : OFF_KS0;
#pragma unroll
            for (int i = 0; i < 8; i++) {
                int idx = tid + i * 256;
                int r = idx >> 5, c4 = (idx & 31) * 4;
                CP_ASYNC16(smb + (uint32_t)(koff + r * KTP + c4) * 4u,
                           Kg + (size_t)((nt + 1) * 64 + r) * HD + c4);
            }
            CP_COMMIT();
        }
        if (nt < mt) { CP_WAIT2(); } else { CP_WAIT1(); }
        __syncthreads();

        uint32_t kb_base = (nt & 1) ? ks_base1 : ks_base0;
        float accS[4][4];
#pragma unroll
        for (int na = 0; na < 4; na++)
#pragma unroll
            for (int u = 0; u < 4; u++) accS[na][u] = 0.0f;
#pragma unroll 4
        for (int ks = 0; ks < 16; ks++) {
            uint32_t ah[4], al[4];
            LDMX4(ah, qhi_base + ks * 32u);
            LDMX4(al, qlo_base + ks * 32u);
#pragma unroll
            for (int pr = 0; pr < 2; pr++) {
                uint32_t kb[4];
                LDMX4(kb, kb_base + (uint32_t)(pr * 16 * KTP) * 4u + ks * 32u);
                mma_tf32(accS[pr * 2],     ah, kb[0], kb[2]);
                mma_tf32(accS[pr * 2],     al, kb[0], kb[2]);
                mma_tf32(accS[pr * 2 + 1], ah, kb[1], kb[3]);
                mma_tf32(accS[pr * 2 + 1], al, kb[1], kb[3]);
            }
        }

        if (nt == mt) {
#pragma unroll
            for (int na = 0; na < 4; na++) {
                int col = wN * 32 + na * 8 + 2 * lc;
                if (col     > r0)     accS[na][0] = -1e30f;
                if (col + 1 > r0)     accS[na][1] = -1e30f;
                if (col     > r0 + 8) accS[na][2] = -1e30f;
                if (col + 1 > r0 + 8) accS[na][3] = -1e30f;
            }
        }

        float mx0 = -1e30f, mx1 = -1e30f;
#pragma unroll
        for (int na = 0; na < 4; na++) {
            mx0 = fmaxf(mx0, fmaxf(accS[na][0], accS[na][1]));
            mx1 = fmaxf(mx1, fmaxf(accS[na][2], accS[na][3]));
        }
        mx0 = fmaxf(mx0, __shfl_xor_sync(0xffffffffu, mx0, 1));
        mx0 = fmaxf(mx0, __shfl_xor_sync(0xffffffffu, mx0, 2));
        mx1 = fmaxf(mx1, __shfl_xor_sync(0xffffffffu, mx1, 1));
        mx1 = fmaxf(mx1, __shfl_xor_sync(0xffffffffu, mx1, 2));
        if ((lane & 3) == 0) {
            wmaxs[wN * 64 + r0]     = mx0;
            wmaxs[wN * 64 + r0 + 8] = mx1;
        }
        __syncthreads();
        float mn0 = fmaxf(m0, fmaxf(wmaxs[r0], wmaxs[64 + r0]));
        float mn1 = fmaxf(m1, fmaxf(wmaxs[r0 + 8], wmaxs[64 + r0 + 8]));
        float a0, a1;
        EX2F(a0, m0 - mn0);
        EX2F(a1, m1 - mn1);
        float s0 = 0.0f, s1 = 0.0f;
#pragma unroll
        for (int na = 0; na < 4; na++) {
            float p00, p01, p10, p11;
            EX2F(p00, accS[na][0] - mn0);
            EX2F(p01, accS[na][1] - mn0);
            EX2F(p10, accS[na][2] - mn1);
            EX2F(p11, accS[na][3] - mn1);
            CVT_TF32(p00, p00); CVT_TF32(p01, p01);
            CVT_TF32(p10, p10); CVT_TF32(p11, p11);
            s0 += p00 + p01; s1 += p10 + p11;
            int col = wN * 32 + na * 8 + 2 * lc;
            *(float2*)(Ps + r0 * PP + col)       = make_float2(p00, p01);
            *(float2*)(Ps + (r0 + 8) * PP + col) = make_float2(p10, p11);
        }
        s0 += __shfl_xor_sync(0xffffffffu, s0, 1);
        s0 += __shfl_xor_sync(0xffffffffu, s0, 2);
        s1 += __shfl_xor_sync(0xffffffffu, s1, 1);
        s1 += __shfl_xor_sync(0xffffffffu, s1, 2);
        if ((lane & 3) == 0) {
            wsums[wN * 64 + r0]     = s0;
            wsums[wN * 64 + r0 + 8] = s1;
        }
        if (nt < mt) { CP_WAIT1(); } else { CP_WAIT0(); }
        __syncthreads();
        l0 = l0 * a0 + wsums[r0] + wsums[64 + r0];
        l1 = l1 * a1 + wsums[r0 + 8] + wsums[64 + r0 + 8];
        m0 = mn0; m1 = mn1;
#pragma unroll
        for (int i = 0; i < 16; i++) {
            O[i][0] *= a0; O[i][1] *= a0; O[i][2] *= a1; O[i][3] *= a1;
        }

#pragma unroll 2
        for (int ks = 0; ks < 8; ks++) {
            uint32_t pf[4];
            LDMX4(pf, ps_base + ks * 32u);
#pragma unroll
            for (int pr = 0; pr < 8; pr++) {
                uint32_t vb[4];
                LDMX4(vb, vt_base + (uint32_t)(pr * 16 * VTP) * 4u + ks * 32u);
                mma_tf32(O[pr * 2],     pf, vb[0], vb[2]);
                mma_tf32(O[pr * 2 + 1], pf, vb[1], vb[3]);
            }
        }
    }

    float i0, i1;
    asm("rcp.approx.f32 %0, %1;" : "=f"(i0) : "f"(l0));
    asm("rcp.approx.f32 %0, %1;" : "=f"(i1) : "f"(l1));
    int tg0 = mt * 64 + r0;
#pragma unroll
    for (int na = 0; na < 16; na++) {
        int col = wN * 128 + na * 8 + 2 * lc;
        *(float2*)(Yg + (size_t)tg0 * 256 + col)       = make_float2(O[na][0] * i0, O[na][1] * i0);
        *(float2*)(Yg + (size_t)(tg0 + 8) * 256 + col) = make_float2(O[na][2] * i1, O[na][3] * i1);
    }
}

// ---------------- combine ----------------
__global__ void combine_kernel(float* __restrict__ out) {
    int t = blockIdx.x, hp = blockIdx.y, b = blockIdx.z;
    int e = threadIdx.x;
    size_t y1i = ((size_t)(b * NH + 2 * hp)     * T_ + t) * 256 + e;
    size_t y2i = ((size_t)(b * NH + 2 * hp + 1) * T_ + t) * 256 + e;
    float y1 = g_Y[y1i], y2 = g_Y[y2i];
    float lam = g_lam[hp];
    float gv = g_gate[((size_t)(b * T_ + t)) * DM + hp * 256 + e];
    float sg = gv / (1.0f + expf(-gv));
    float yv = (y1 - lam * y2) * sg;

    __shared__ float red[8];
    float s = yv * yv;
#pragma unroll
    for (int off = 16; off > 0; off >>= 1)
        s += __shfl_xor_sync(0xffffffffu, s, off);
    if ((e & 31) == 0) red[e >> 5] = s;
    __syncthreads();
    float tot = 0.0f;
#pragma unroll
    for (int w = 0; w < 8; w++) tot += red[w];
    float r = rsqrtf(tot * (1.0f / 256.0f) + 1e-6f) * ONE_MINUS_LI;
    out[((size_t)(b * T_ + t)) * DM + hp * 256 + e] = yv * r;
}

// ---------------- launch ----------------
extern "C" void kernel_launch(void* const* d_in, const int* in_sizes, int n_in,
                              void* d_out, int out_size) {
    const float* x    = (const float*)d_in[0];
    const float* Wqkv = (const float*)d_in[1];
    const float* lq1  = (const float*)d_in[2];
    const float* lk1  = (const float*)d_in[3];
    const float* lq2  = (const float*)d_in[4];
    const float* lk2  = (const float*)d_in[5];
    const float* Wg   = (const float*)d_in[6];
    float* out = (float*)d_out;

    float *qkv_p, *gate_p;
    __nv_bfloat16 *xhi_p, *xlo_p, *wqh_p, *wql_p, *wgh_p, *wgl_p;
    cudaGetSymbolAddress((void**)&qkv_p,  g_qkv);
    cudaGetSymbolAddress((void**)&gate_p, g_gate);
    cudaGetSymbolAddress((void**)&xhi_p,  g_Xhi);
    cudaGetSymbolAddress((void**)&xlo_p,  g_Xlo);
    cudaGetSymbolAddress((void**)&wqh_p,  g_WqHiT);
    cudaGetSymbolAddress((void**)&wql_p,  g_WqLoT);
    cudaGetSymbolAddress((void**)&wgh_p,  g_WgHiT);
    cudaGetSymbolAddress((void**)&wgl_p,  g_WgLoT);

    // 0) split x, transpose+split weights (bf16 hi/lo)
    int nx4 = B_ * T_ * DM / 4;
    splitx_bf16_kernel<<<(nx4 + 255) / 256, 256>>>(x, xhi_p, xlo_p, nx4);
    wsplit_t_kernel<<<dim3(QKV_N / 32, DM / 32), dim3(32, 8)>>>(Wqkv, wqh_p, wql_p, DM, QKV_N);
    wsplit_t_kernel<<<dim3(DM / 32,    DM / 32), dim3(32, 8)>>>(Wg,   wgh_p, wgl_p, DM, DM);

    // 1) projections (bf16 double-double mma)
    cudaFuncSetAttribute(gemm_bf16_kernel, cudaFuncAttributeMaxDynamicSharedMemorySize, GEMM_SMEM);
    gemm_bf16_kernel<<<dim3(QKV_N / GBN, (B_ * T_) / GBM), 256, GEMM_SMEM>>>(xhi_p, xlo_p, wqh_p, wql_p, qkv_p, QKV_N, DM);
    gemm_bf16_kernel<<<dim3(DM / GBN,    (B_ * T_) / GBM), 256, GEMM_SMEM>>>(xhi_p, xlo_p, wgh_p, wgl_p, gate_p, DM, DM);

    // 2) rmsnorm + rope
    prep_kernel<<<dim3(T_, NH, B_), 128>>>();
    // 3) V transpose
    vtrans_kernel<<<dim3(T_ / 32, 256 / 32, B_ * HP_), dim3(32, 8)>>>();
    // 4) lambda
    lam_kernel<<<1, dim3(32, 8)>>>(lq1, lk1, lq2, lk2);
    // 5) attention
    cudaFuncSetAttribute(attn_kernel, cudaFuncAttributeMaxDynamicSharedMemorySize, ATT_SMEM);
    attn_kernel<<<dim3(T_ / 64, NH, B_), 256, ATT_SMEM>>>();
    // 6) combine
    combine_kernel<<<dim3(T_, HP_, B_), 256>>>(out);
}

// round 7
// speedup vs baseline: 1.1207x; 1.1207x over previous
#include <cuda_runtime.h>
#include <cuda_bf16.h>
#include <math.h>
#include <cstdint>

#define B_   2
#define T_   2048
#define DM   2048
#define NH   16
#define HD   128
#define HP_  8
#define QKV_N 6144
#define LAMBDA_INIT  0.7008206670670481f
#define ONE_MINUS_LI 0.2991793329329519f

// ---------------- scratch ----------------
__device__ float g_qkv[(size_t)B_ * T_ * QKV_N];
__device__ float g_gate[(size_t)B_ * T_ * DM];
__device__ float g_Q[(size_t)B_ * NH * T_ * HD];
__device__ float g_K[(size_t)B_ * NH * T_ * HD];
__device__ float g_V[(size_t)B_ * HP_ * T_ * 256];
__device__ float g_Vt[(size_t)B_ * HP_ * 256 * T_];
__device__ float g_Y[(size_t)B_ * NH * T_ * 256];
__device__ float g_lam[HP_];
__device__ __nv_bfloat16 g_Xhi[(size_t)B_ * T_ * DM];
__device__ __nv_bfloat16 g_Xlo[(size_t)B_ * T_ * DM];
__device__ __nv_bfloat16 g_WqHiT[(size_t)QKV_N * DM];
__device__ __nv_bfloat16 g_WqLoT[(size_t)QKV_N * DM];
__device__ __nv_bfloat16 g_WgHiT[(size_t)DM * DM];
__device__ __nv_bfloat16 g_WgLoT[(size_t)DM * DM];

// ================= helpers =================
__device__ __forceinline__ uint32_t smem_u32(const void* p) {
    uint32_t a;
    asm("{ .reg .u64 t; cvta.to.shared.u64 t, %1; cvt.u32.u64 %0, t; }" : "=r"(a) : "l"(p));
    return a;
}
#define CP_ASYNC16(dst, src) \
    asm volatile("cp.async.cg.shared.global [%0], [%1], 16;" :: "r"(dst), "l"(src) : "memory")
#define CP_COMMIT() asm volatile("cp.async.commit_group;" ::: "memory")
#define CP_WAIT0()  asm volatile("cp.async.wait_group 0;" ::: "memory")
#define CP_WAIT1()  asm volatile("cp.async.wait_group 1;" ::: "memory")
#define CP_WAIT2()  asm volatile("cp.async.wait_group 2;" ::: "memory")
#define CVT_TF32(d, s) asm("cvt.rna.tf32.f32 %0, %1;" : "=f"(d) : "f"(s))
#define EX2F(d, s)     asm("ex2.approx.f32 %0, %1;" : "=f"(d) : "f"(s))
#define LDMX4(r, addr) \
    asm volatile("ldmatrix.sync.aligned.m8n8.x4.shared.b16 {%0,%1,%2,%3}, [%4];" \
        : "=r"((r)[0]), "=r"((r)[1]), "=r"((r)[2]), "=r"((r)[3]) : "r"(addr))

__device__ __forceinline__ void mma_tf32(float* c, const uint32_t* a, uint32_t b0, uint32_t b1) {
    asm volatile(
        "mma.sync.aligned.m16n8k8.row.col.f32.tf32.tf32.f32 "
        "{%0,%1,%2,%3}, {%4,%5,%6,%7}, {%8,%9}, {%0,%1,%2,%3};"
        : "+f"(c[0]), "+f"(c[1]), "+f"(c[2]), "+f"(c[3])
        : "r"(a[0]), "r"(a[1]), "r"(a[2]), "r"(a[3]), "r"(b0), "r"(b1));
}
__device__ __forceinline__ void mma_bf16(float* c, const uint32_t* a, uint32_t b0, uint32_t b1) {
    asm volatile(
        "mma.sync.aligned.m16n8k16.row.col.f32.bf16.bf16.f32 "
        "{%0,%1,%2,%3}, {%4,%5,%6,%7}, {%8,%9}, {%0,%1,%2,%3};"
        : "+f"(c[0]), "+f"(c[1]), "+f"(c[2]), "+f"(c[3])
        : "r"(a[0]), "r"(a[1]), "r"(a[2]), "r"(a[3]), "r"(b0), "r"(b1));
}

// ================= bf16 DD GEMM, k32 stages, 2-stage pipeline =================
#define NST 2
#define GBM 128
#define GBN 128
#define APB 80                       // smem row pitch bytes (32 bf16 = 64B used + 16 pad)
#define A_SB (128 * APB)             // 10240 B per split
#define STAGE_B (4 * A_SB)           // 40960 B
#define GEMM_SMEM (NST * STAGE_B)    // 81920 B

__device__ __forceinline__ void gemm_stage_load(const __nv_bfloat16* __restrict__ Ahi,
                                                const __nv_bfloat16* __restrict__ Alo,
                                                const __nv_bfloat16* __restrict__ Bhi,
                                                const __nv_bfloat16* __restrict__ Blo,
                                                int K, int m0, int n0, int kt,
                                                uint32_t sbase, int tid) {
#pragma unroll
    for (int i = 0; i < 2; i++) {
        int c = tid + i * 256;
        int r = c >> 2, c16 = c & 3;
        uint32_t off = (uint32_t)(r * APB + c16 * 16);
        size_t ga = (size_t)(m0 + r) * K + kt * 32 + c16 * 8;
        size_t gb = (size_t)(n0 + r) * K + kt * 32 + c16 * 8;
        CP_ASYNC16(sbase + off,              Ahi + ga);
        CP_ASYNC16(sbase + A_SB + off,       Alo + ga);
        CP_ASYNC16(sbase + 2 * A_SB + off,   Bhi + gb);
        CP_ASYNC16(sbase + 3 * A_SB + off,   Blo + gb);
    }
    CP_COMMIT();
}

__global__ void __launch_bounds__(256, 2) gemm_bf16_kernel(const __nv_bfloat16* __restrict__ Ahi,
                                                           const __nv_bfloat16* __restrict__ Alo,
                                                           const __nv_bfloat16* __restrict__ Bhi,
                                                           const __nv_bfloat16* __restrict__ Blo,
                                                           float* __restrict__ C,
                                                           int N, int K) {
    extern __shared__ char smraw[];
    uint32_t sm_b = smem_u32(smraw);
    const int tid = threadIdx.x;
    const int wid = tid >> 5;
    const int lane = tid & 31;
    const int warpM = wid & 1;
    const int warpN = wid >> 1;
    const int m0 = blockIdx.y * GBM;
    const int n0 = blockIdx.x * GBN;
    const int NT = K / 32;
    const int lr = lane >> 2;
    const int lc = lane & 3;
    const int lm_row = lane & 15;
    const int lm_hi  = (lane >> 4) * 16;

    float acc[4][4][4];
#pragma unroll
    for (int i = 0; i < 4; i++)
#pragma unroll
        for (int j = 0; j < 4; j++)
#pragma unroll
            for (int u = 0; u < 4; u++) acc[i][j][u] = 0.0f;

    gemm_stage_load(Ahi, Alo, Bhi, Blo, K, m0, n0, 0, sm_b, tid);

    for (int kt = 0; kt < NT; kt++) {
        if (kt + 1 < NT)
            gemm_stage_load(Ahi, Alo, Bhi, Blo, K, m0, n0, kt + 1,
                            sm_b + (uint32_t)(((kt + 1) & 1) * STAGE_B), tid);
        if (kt + 1 < NT) { CP_WAIT1(); } else { CP_WAIT0(); }
        __syncthreads();

        uint32_t sA = sm_b + (uint32_t)((kt & 1) * STAGE_B);
        uint32_t a_base = sA + (uint32_t)((warpM * 64 + lm_row) * APB + lm_hi);
        uint32_t b_base = sA + 2u * A_SB + (uint32_t)((warpN * 32 + lm_row) * APB + lm_hi);

#pragma unroll
        for (int half = 0; half < 2; half++) {
            uint32_t hb = (uint32_t)(half * 32);
            uint32_t bh[2][4], bl[2][4];
#pragma unroll
            for (int nb = 0; nb < 2; nb++) {
                LDMX4(bh[nb], b_base + (uint32_t)(nb * 16 * APB) + hb);
                LDMX4(bl[nb], b_base + (uint32_t)(nb * 16 * APB) + hb + A_SB);
            }
#pragma unroll
            for (int ma = 0; ma < 4; ma++) {
                uint32_t ah[4], al[4];
                uint32_t addr = a_base + (uint32_t)(ma * 16 * APB) + hb;
                LDMX4(ah, addr);
                LDMX4(al, addr + A_SB);
#pragma unroll
                for (int na = 0; na < 4; na++) {
                    int nb = na >> 1, j = na & 1;
                    mma_bf16(acc[ma][na], ah, bh[nb][j], bh[nb][j + 2]);
                    mma_bf16(acc[ma][na], ah, bl[nb][j], bl[nb][j + 2]);
                    mma_bf16(acc[ma][na], al, bh[nb][j], bh[nb][j + 2]);
                }
            }
        }
        __syncthreads();
    }

#pragma unroll
    for (int ma = 0; ma < 4; ma++) {
        int r0 = m0 + warpM * 64 + ma * 16 + lr;
#pragma unroll
        for (int na = 0; na < 4; na++) {
            int c0 = n0 + warpN * 32 + na * 8 + lc * 2;
            *(float2*)(C + (size_t)r0 * N + c0)       = make_float2(acc[ma][na][0], acc[ma][na][1]);
            *(float2*)(C + (size_t)(r0 + 8) * N + c0) = make_float2(acc[ma][na][2], acc[ma][na][3]);
        }
    }
}

// ================= pre-kernels =================
__global__ void splitx_bf16_kernel(const float* __restrict__ x,
                                   __nv_bfloat16* __restrict__ xhi,
                                   __nv_bfloat16* __restrict__ xlo, int n4) {
    int i = blockIdx.x * blockDim.x + threadIdx.x;
    if (i < n4) {
        float4 v = ((const float4*)x)[i];
        float f[4] = {v.x, v.y, v.z, v.w};
        __nv_bfloat16 h[4], l[4];
#pragma unroll
        for (int j = 0; j < 4; j++) {
            h[j] = __float2bfloat16_rn(f[j]);
            l[j] = __float2bfloat16_rn(f[j] - __bfloat162float(h[j]));
        }
        ((uint2*)xhi)[i] = *(uint2*)h;
        ((uint2*)xlo)[i] = *(uint2*)l;
    }
}

__global__ void wsplit_t_kernel(const float* __restrict__ W,
                                __nv_bfloat16* __restrict__ WhiT,
                                __nv_bfloat16* __restrict__ WloT,
                                int K, int Nc) {
    __shared__ float tile[32][33];
    int n0 = blockIdx.x * 32, k0 = blockIdx.y * 32;
    int tx = threadIdx.x, ty = threadIdx.y;
#pragma unroll
    for (int i = 0; i < 4; i++)
        tile[ty + i * 8][tx] = W[(size_t)(k0 + ty + i * 8) * Nc + n0 + tx];
    __syncthreads();
#pragma unroll
    for (int i = 0; i < 4; i++) {
        float v = tile[tx][ty + i * 8];
        __nv_bfloat16 h = __float2bfloat16_rn(v);
        __nv_bfloat16 l = __float2bfloat16_rn(v - __bfloat162float(h));
        size_t o = (size_t)(n0 + ty + i * 8) * K + k0 + tx;
        WhiT[o] = h;
        WloT[o] = l;
    }
}

// ---------------- prep: rmsnorm(q,k) + RoPE ----------------
__global__ void prep_kernel() {
    int t = blockIdx.x, h = blockIdx.y, b = blockIdx.z;
    int d = threadIdx.x;
    const float* p = g_qkv + ((size_t)(b * T_ + t)) * QKV_N + h * 384;
    float qv = p[d], kv = p[128 + d], vv = p[256 + d];

    __shared__ float redq[4], redk[4];
    __shared__ float qs[128], ks[128];
    float q2 = qv * qv, k2 = kv * kv;
#pragma unroll
    for (int off = 16; off > 0; off >>= 1) {
        q2 += __shfl_xor_sync(0xffffffffu, q2, off);
        k2 += __shfl_xor_sync(0xffffffffu, k2, off);
    }
    if ((d & 31) == 0) { redq[d >> 5] = q2; redk[d >> 5] = k2; }
    __syncthreads();
    float sq = redq[0] + redq[1] + redq[2] + redq[3];
    float sk = redk[0] + redk[1] + redk[2] + redk[3];
    float qn = qv * rsqrtf(sq * (1.0f / 128.0f) + 1e-6f);
    float kn = kv * rsqrtf(sk * (1.0f / 128.0f) + 1e-6f);
    qs[d] = qn; ks[d] = kn;
    __syncthreads();

    int dd = d & 63;
    float freq = (float)t * expf(-(float)dd * (9.210340371976184f / 64.0f));
    float c = cosf(freq), s = sinf(freq);
    float qr, kr;
    if (d < 64) { qr =  qs[d] * c + qs[d + 64] * s;  kr =  ks[d] * c + ks[d + 64] * s; }
    else        { qr = -qs[dd] * s + qs[d] * c;      kr = -ks[dd] * s + ks[d] * c;     }

    const float QSCL = 0.08838834764831845f * 1.44269504088896340f;
    size_t qi = ((size_t)(b * NH + h) * T_ + t) * HD + d;
    g_Q[qi] = qr * QSCL;
    float krr; CVT_TF32(krr, kr);
    g_K[qi] = krr;
    float vvr; CVT_TF32(vvr, vv);
    size_t vi = ((size_t)(b * HP_ + (h >> 1)) * T_ + t) * 256 + (size_t)(h & 1) * 128 + d;
    g_V[vi] = vvr;
}

// ---------------- V transpose ----------------
__global__ void vtrans_kernel() {
    __shared__ float tile[32][33];
    int t0 = blockIdx.x * 32, e0 = blockIdx.y * 32, bhp = blockIdx.z;
    const float* src = g_V + (size_t)bhp * T_ * 256;
    float* dst = g_Vt + (size_t)bhp * 256 * T_;
    int tx = threadIdx.x, ty = threadIdx.y;
#pragma unroll
    for (int i = 0; i < 4; i++)
        tile[ty + i * 8][tx] = src[(size_t)(t0 + ty + i * 8) * 256 + e0 + tx];
    __syncthreads();
#pragma unroll
    for (int i = 0; i < 4; i++)
        dst[(size_t)(e0 + ty + i * 8) * T_ + t0 + tx] = tile[tx][ty + i * 8];
}

// ---------------- lambda ----------------
__global__ void lam_kernel(const float* __restrict__ lq1, const float* __restrict__ lk1,
                           const float* __restrict__ lq2, const float* __restrict__ lk2) {
    int hp = threadIdx.y;
    int lane = threadIdx.x;
    float s1 = lq1[hp*64 + lane] * lk1[hp*64 + lane] + lq1[hp*64 + lane + 32] * lk1[hp*64 + lane + 32];
    float s2 = lq2[hp*64 + lane] * lk2[hp*64 + lane] + lq2[hp*64 + lane + 32] * lk2[hp*64 + lane + 32];
#pragma unroll
    for (int off = 16; off > 0; off >>= 1) {
        s1 += __shfl_xor_sync(0xffffffffu, s1, off);
        s2 += __shfl_xor_sync(0xffffffffu, s2, off);
    }
    if (lane == 0) g_lam[hp] = expf(s1) - expf(s2) + LAMBDA_INIT;
}

// ---------------- flash attention, tf32 mma, single-Q ----------------
#define QP 132
#define KTP 132
#define VTP 76
#define PP 68
#define OFF_QS  0
#define OFF_KS0 (OFF_QS + 64 * QP)
#define OFF_KS1 (OFF_KS0 + 64 * KTP)
#define OFF_VT  (OFF_KS1 + 64 * KTP)
#define OFF_PS  (OFF_VT + 256 * VTP)
#define OFF_WMAX (OFF_PS + 64 * PP)
#define OFF_WSUM (OFF_WMAX + 128)
#define ATT_SMEM ((OFF_WSUM + 128) * 4)

__global__ void __launch_bounds__(256, 1) attn_kernel() {
    const int mt = gridDim.x - 1 - blockIdx.x;
    const int h = blockIdx.y, b = blockIdx.z;
    const int tid = threadIdx.x, wid = tid >> 5, lane = tid & 31;
    const int wM = wid & 3, wN = wid >> 2;
    const int lr = lane >> 2, lc = lane & 3;
    const int r0 = wM * 16 + lr;
    const int x_row = ((lane >> 3) & 1) * 8 + (lane & 7);
    const int x_col = (lane >> 4) * 4;

    extern __shared__ float sm[];
    uint32_t smb = smem_u32(sm);
    float* Ps = sm + OFF_PS;
    float* wmaxs = sm + OFF_WMAX;
    float* wsums = sm + OFF_WSUM;

    const float* Qg  = g_Q  + ((size_t)(b * NH + h) * T_ + (size_t)mt * 64) * HD;
    const float* Kg  = g_K  + (size_t)(b * NH + h) * T_ * HD;
    const float* Vtg = g_Vt + (size_t)(b * HP_ + (h >> 1)) * 256 * T_;
    float*       Yg  = g_Y  + (size_t)(b * NH + h) * T_ * 256;

#pragma unroll
    for (int i = 0; i < 8; i++) {
        int idx = tid + i * 256;
        int r = idx >> 5, c4 = (idx & 31) * 4;
        CP_ASYNC16(smb + (uint32_t)(OFF_KS0 + r * KTP + c4) * 4u,
                   Kg + (size_t)r * HD + c4);
    }
    CP_COMMIT();

    // Q tile (rounded tf32, single buffer)
    for (int c = tid; c < 64 * 32; c += 256) {
        int q = c >> 5, d4 = (c & 31) * 4;
        float4 v = *(const float4*)(Qg + (size_t)q * HD + d4);
        CVT_TF32(v.x, v.x); CVT_TF32(v.y, v.y);
        CVT_TF32(v.z, v.z); CVT_TF32(v.w, v.w);
        *(float4*)(sm + OFF_QS + q * QP + d4) = v;
    }

    float O[16][4];
#pragma unroll
    for (int i = 0; i < 16; i++)
#pragma unroll
        for (int j = 0; j < 4; j++) O[i][j] = 0.0f;
    float m0 = -1e30f, m1 = -1e30f, l0 = 0.0f, l1 = 0.0f;

    const uint32_t qs_base  = smb + (uint32_t)(OFF_QS + (wM * 16 + x_row) * QP + x_col) * 4u;
    const uint32_t ps_base  = smb + (uint32_t)(OFF_PS + (wM * 16 + x_row) * PP + x_col) * 4u;
    const uint32_t vt_base  = smb + (uint32_t)(OFF_VT + (wN * 128 + x_row) * VTP + x_col) * 4u;
    const uint32_t ks_base0 = smb + (uint32_t)(OFF_KS0 + (wN * 32 + x_row) * KTP + x_col) * 4u;
    const uint32_t ks_base1 = smb + (uint32_t)(OFF_KS1 + (wN * 32 + x_row) * KTP + x_col) * 4u;

    for (int nt = 0; nt <= mt; nt++) {
        __syncthreads();
#pragma unroll
        for (int i = 0; i < 16; i++) {
            int idx = tid + i * 256;
            int r = idx >> 4, c4 = (idx & 15) * 4;
            CP_ASYNC16(smb + (uint32_t)(OFF_VT + r * VTP + c4) * 4u,
                       Vtg + (size_t)r * T_ + nt * 64 + c4);
        }
        CP_COMMIT();
        if (nt < mt) {
            int koff = ((nt + 1) & 1) ? OFF_KS1 : OFF_KS0;
#pragma unroll
            for (int i = 0; i < 8; i++) {
                int idx = tid + i * 256;
                int r = idx >> 5, c4 = (idx & 31) * 4;
                CP_ASYNC16(smb + (uint32_t)(koff + r * KTP + c4) * 4u,
                           Kg + (size_t)((nt + 1) * 64 + r) * HD + c4);
            }
            CP_COMMIT();
        }
        if (nt < mt) { CP_WAIT2(); } else { CP_WAIT1(); }
        __syncthreads();

        // ---- S = Q K^T, single tf32 ----
        uint32_t kb_base = (nt & 1) ? ks_base1 : ks_base0;
        float accS[4][4];
#pragma unroll
        for (int na = 0; na < 4; na++)
#pragma unroll
            for (int u = 0; u < 4; u++) accS[na][u] = 0.0f;
#pragma unroll 4
        for (int ks = 0; ks < 16; ks++) {
            uint32_t ah[4];
            LDMX4(ah, qs_base + ks * 32u);
#pragma unroll
            for (int pr = 0; pr < 2; pr++) {
                uint32_t kb[4];
                LDMX4(kb, kb_base + (uint32_t)(pr * 16 * KTP) * 4u + ks * 32u);
                mma_tf32(accS[pr * 2],     ah, kb[0], kb[2]);
                mma_tf32(accS[pr * 2 + 1], ah, kb[1], kb[3]);
            }
        }

        if (nt == mt) {
#pragma unroll
            for (int na = 0; na < 4; na++) {
                int col = wN * 32 + na * 8 + 2 * lc;
                if (col     > r0)     accS[na][0] = -1e30f;
                if (col + 1 > r0)     accS[na][1] = -1e30f;
                if (col     > r0 + 8) accS[na][2] = -1e30f;
                if (col + 1 > r0 + 8) accS[na][3] = -1e30f;
            }
        }

        float mx0 = -1e30f, mx1 = -1e30f;
#pragma unroll
        for (int na = 0; na < 4; na++) {
            mx0 = fmaxf(mx0, fmaxf(accS[na][0], accS[na][1]));
            mx1 = fmaxf(mx1, fmaxf(accS[na][2], accS[na][3]));
        }
        mx0 = fmaxf(mx0, __shfl_xor_sync(0xffffffffu, mx0, 1));
        mx0 = fmaxf(mx0, __shfl_xor_sync(0xffffffffu, mx0, 2));
        mx1 = fmaxf(mx1, __shfl_xor_sync(0xffffffffu, mx1, 1));
        mx1 = fmaxf(mx1, __shfl_xor_sync(0xffffffffu, mx1, 2));
        if ((lane & 3) == 0) {
            wmaxs[wN * 64 + r0]     = mx0;
            wmaxs[wN * 64 + r0 + 8] = mx1;
        }
        __syncthreads();
        float mn0 = fmaxf(m0, fmaxf(wmaxs[r0], wmaxs[64 + r0]));
        float mn1 = fmaxf(m1, fmaxf(wmaxs[r0 + 8], wmaxs[64 + r0 + 8]));
        float a0, a1;
        EX2F(a0, m0 - mn0);
        EX2F(a1, m1 - mn1);
        float s0 = 0.0f, s1 = 0.0f;
#pragma unroll
        for (int na = 0; na < 4; na++) {
            float p00, p01, p10, p11;
            EX2F(p00, accS[na][0] - mn0);
            EX2F(p01, accS[na][1] - mn0);
            EX2F(p10, accS[na][2] - mn1);
            EX2F(p11, accS[na][3] - mn1);
            CVT_TF32(p00, p00); CVT_TF32(p01, p01);
            CVT_TF32(p10, p10); CVT_TF32(p11, p11);
            s0 += p00 + p01; s1 += p10 + p11;
            int col = wN * 32 + na * 8 + 2 * lc;
            *(float2*)(Ps + r0 * PP + col)       = make_float2(p00, p01);
            *(float2*)(Ps + (r0 + 8) * PP + col) = make_float2(p10, p11);
        }
        s0 += __shfl_xor_sync(0xffffffffu, s0, 1);
        s0 += __shfl_xor_sync(0xffffffffu, s0, 2);
        s1 += __shfl_xor_sync(0xffffffffu, s1, 1);
        s1 += __shfl_xor_sync(0xffffffffu, s1, 2);
        if ((lane & 3) == 0) {
            wsums[wN * 64 + r0]     = s0;
            wsums[wN * 64 + r0 + 8] = s1;
        }
        if (nt < mt) { CP_WAIT1(); } else { CP_WAIT0(); }
        __syncthreads();
        l0 = l0 * a0 + wsums[r0] + wsums[64 + r0];
        l1 = l1 * a1 + wsums[r0 + 8] + wsums[64 + r0 + 8];
        m0 = mn0; m1 = mn1;
#pragma unroll
        for (int i = 0; i < 16; i++) {
            O[i][0] *= a0; O[i][1] *= a0; O[i][2] *= a1; O[i][3] *= a1;
        }

#pragma unroll 2
        for (int ks = 0; ks < 8; ks++) {
            uint32_t pf[4];
            LDMX4(pf, ps_base + ks * 32u);
#pragma unroll
            for (int pr = 0; pr < 8; pr++) {
                uint32_t vb[4];
                LDMX4(vb, vt_base + (uint32_t)(pr * 16 * VTP) * 4u + ks * 32u);
                mma_tf32(O[pr * 2],     pf, vb[0], vb[2]);
                mma_tf32(O[pr * 2 + 1], pf, vb[1], vb[3]);
            }
        }
    }

    float i0, i1;
    asm("rcp.approx.f32 %0, %1;" : "=f"(i0) : "f"(l0));
    asm("rcp.approx.f32 %0, %1;" : "=f"(i1) : "f"(l1));
    int tg0 = mt * 64 + r0;
#pragma unroll
    for (int na = 0; na < 16; na++) {
        int col = wN * 128 + na * 8 + 2 * lc;
        *(float2*)(Yg + (size_t)tg0 * 256 + col)       = make_float2(O[na][0] * i0, O[na][1] * i0);
        *(float2*)(Yg + (size_t)(tg0 + 8) * 256 + col) = make_float2(O[na][2] * i1, O[na][3] * i1);
    }
}

// ---------------- combine ----------------
__global__ void combine_kernel(float* __restrict__ out) {
    int t = blockIdx.x, hp = blockIdx.y, b = blockIdx.z;
    int e = threadIdx.x;
    size_t y1i = ((size_t)(b * NH + 2 * hp)     * T_ + t) * 256 + e;
    size_t y2i = ((size_t)(b * NH + 2 * hp + 1) * T_ + t) * 256 + e;
    float y1 = g_Y[y1i], y2 = g_Y[y2i];
    float lam = g_lam[hp];
    float gv = g_gate[((size_t)(b * T_ + t)) * DM + hp * 256 + e];
    float sg = gv / (1.0f + expf(-gv));
    float yv = (y1 - lam * y2) * sg;

    __shared__ float red[8];
    float s = yv * yv;
#pragma unroll
    for (int off = 16; off > 0; off >>= 1)
        s += __shfl_xor_sync(0xffffffffu, s, off);
    if ((e & 31) == 0) red[e >> 5] = s;
    __syncthreads();
    float tot = 0.0f;
#pragma unroll
    for (int w = 0; w < 8; w++) tot += red[w];
    float r = rsqrtf(tot * (1.0f / 256.0f) + 1e-6f) * ONE_MINUS_LI;
    out[((size_t)(b * T_ + t)) * DM + hp * 256 + e] = yv * r;
}

// ---------------- launch ----------------
extern "C" void kernel_launch(void* const* d_in, const int* in_sizes, int n_in,
                              void* d_out, int out_size) {
    const float* x    = (const float*)d_in[0];
    const float* Wqkv = (const float*)d_in[1];
    const float* lq1  = (const float*)d_in[2];
    const float* lk1  = (const float*)d_in[3];
    const float* lq2  = (const float*)d_in[4];
    const float* lk2  = (const float*)d_in[5];
    const float* Wg   = (const float*)d_in[6];
    float* out = (float*)d_out;

    float *qkv_p, *gate_p;
    __nv_bfloat16 *xhi_p, *xlo_p, *wqh_p, *wql_p, *wgh_p, *wgl_p;
    cudaGetSymbolAddress((void**)&qkv_p,  g_qkv);
    cudaGetSymbolAddress((void**)&gate_p, g_gate);
    cudaGetSymbolAddress((void**)&xhi_p,  g_Xhi);
    cudaGetSymbolAddress((void**)&xlo_p,  g_Xlo);
    cudaGetSymbolAddress((void**)&wqh_p,  g_WqHiT);
    cudaGetSymbolAddress((void**)&wql_p,  g_WqLoT);
    cudaGetSymbolAddress((void**)&wgh_p,  g_WgHiT);
    cudaGetSymbolAddress((void**)&wgl_p,  g_WgLoT);

    int nx4 = B_ * T_ * DM / 4;
    splitx_bf16_kernel<<<(nx4 + 255) / 256, 256>>>(x, xhi_p, xlo_p, nx4);
    wsplit_t_kernel<<<dim3(QKV_N / 32, DM / 32), dim3(32, 8)>>>(Wqkv, wqh_p, wql_p, DM, QKV_N);
    wsplit_t_kernel<<<dim3(DM / 32,    DM / 32), dim3(32, 8)>>>(Wg,   wgh_p, wgl_p, DM, DM);

    cudaFuncSetAttribute(gemm_bf16_kernel, cudaFuncAttributeMaxDynamicSharedMemorySize, GEMM_SMEM);
    gemm_bf16_kernel<<<dim3(QKV_N / GBN, (B_ * T_) / GBM), 256, GEMM_SMEM>>>(xhi_p, xlo_p, wqh_p, wql_p, qkv_p, QKV_N, DM);
    gemm_bf16_kernel<<<dim3(DM / GBN,    (B_ * T_) / GBM), 256, GEMM_SMEM>>>(xhi_p, xlo_p, wgh_p, wgl_p, gate_p, DM, DM);

    prep_kernel<<<dim3(T_, NH, B_), 128>>>();
    vtrans_kernel<<<dim3(T_ / 32, 256 / 32, B_ * HP_), dim3(32, 8)>>>();
    lam_kernel<<<1, dim3(32, 8)>>>(lq1, lk1, lq2, lk2);
    cudaFuncSetAttribute(attn_kernel, cudaFuncAttributeMaxDynamicSharedMemorySize, ATT_SMEM);
    attn_kernel<<<dim3(T_ / 64, NH, B_), 256, ATT_SMEM>>>();
    combine_kernel<<<dim3(T_, HP_, B_), 256>>>(out);
}

// round 8
// speedup vs baseline: 1.4718x; 1.3133x over previous
#include <cuda_runtime.h>
#include <cuda_fp16.h>
#include <math.h>
#include <cstdint>

#define B_   2
#define T_   2048
#define DM   2048
#define NH   16
#define HD   128
#define HP_  8
#define QKV_N 6144
#define CN   8192     // fused GEMM N (qkv | gate)
#define LAMBDA_INIT  0.7008206670670481f
#define ONE_MINUS_LI 0.2991793329329519f

// ---------------- scratch ----------------
__device__ float g_C[(size_t)B_ * T_ * CN];        // fused [qkv | gate] output
__device__ float g_Q[(size_t)B_ * NH * T_ * HD];
__device__ float g_K[(size_t)B_ * NH * T_ * HD];
__device__ float g_V[(size_t)B_ * HP_ * T_ * 256];
__device__ float g_Vt[(size_t)B_ * HP_ * 256 * T_];
__device__ float g_Y[(size_t)B_ * NH * T_ * 256];
__device__ float g_lam[HP_];
__device__ __half g_Xhi[(size_t)B_ * T_ * DM];
__device__ __half g_Xlo[(size_t)B_ * T_ * DM];
__device__ __half g_WT[(size_t)CN * DM];           // [8192][2048] f16 (rows 0..6143 Wqkv^T, 6144.. Wg^T)

// ================= helpers =================
__device__ __forceinline__ uint32_t smem_u32(const void* p) {
    uint32_t a;
    asm("{ .reg .u64 t; cvta.to.shared.u64 t, %1; cvt.u32.u64 %0, t; }" : "=r"(a) : "l"(p));
    return a;
}
#define CP_ASYNC16(dst, src) \
    asm volatile("cp.async.cg.shared.global [%0], [%1], 16;" :: "r"(dst), "l"(src) : "memory")
#define CP_COMMIT() asm volatile("cp.async.commit_group;" ::: "memory")
#define CP_WAIT0()  asm volatile("cp.async.wait_group 0;" ::: "memory")
#define CP_WAIT1()  asm volatile("cp.async.wait_group 1;" ::: "memory")
#define CP_WAIT2()  asm volatile("cp.async.wait_group 2;" ::: "memory")
#define CVT_TF32(d, s) asm("cvt.rna.tf32.f32 %0, %1;" : "=f"(d) : "f"(s))
#define EX2F(d, s)     asm("ex2.approx.f32 %0, %1;" : "=f"(d) : "f"(s))
#define LDMX4(r, addr) \
    asm volatile("ldmatrix.sync.aligned.m8n8.x4.shared.b16 {%0,%1,%2,%3}, [%4];" \
        : "=r"((r)[0]), "=r"((r)[1]), "=r"((r)[2]), "=r"((r)[3]) : "r"(addr))

__device__ __forceinline__ void mma_tf32(float* c, const uint32_t* a, uint32_t b0, uint32_t b1) {
    asm volatile(
        "mma.sync.aligned.m16n8k8.row.col.f32.tf32.tf32.f32 "
        "{%0,%1,%2,%3}, {%4,%5,%6,%7}, {%8,%9}, {%0,%1,%2,%3};"
        : "+f"(c[0]), "+f"(c[1]), "+f"(c[2]), "+f"(c[3])
        : "r"(a[0]), "r"(a[1]), "r"(a[2]), "r"(a[3]), "r"(b0), "r"(b1));
}
__device__ __forceinline__ void mma_f16(float* c, const uint32_t* a, uint32_t b0, uint32_t b1) {
    asm volatile(
        "mma.sync.aligned.m16n8k16.row.col.f32.f16.f16.f32 "
        "{%0,%1,%2,%3}, {%4,%5,%6,%7}, {%8,%9}, {%0,%1,%2,%3};"
        : "+f"(c[0]), "+f"(c[1]), "+f"(c[2]), "+f"(c[3])
        : "r"(a[0]), "r"(a[1]), "r"(a[2]), "r"(a[3]), "r"(b0), "r"(b1));
}

// ================= f16 split-A GEMM: C = (Ahi+Alo) @ Bhi^T, k32 stages =================
#define GBM 128
#define GBN 128
#define APB 80                       // smem row pitch bytes (32 f16 = 64B + 16 pad)
#define A_SB (128 * APB)             // 10240 B per operand buffer
#define STAGE_B (3 * A_SB)           // Ahi, Alo, B = 30720 B
#define GEMM_SMEM (2 * STAGE_B)      // 61440 B

__device__ __forceinline__ void gemm_stage_load(const __half* __restrict__ Ahi,
                                                const __half* __restrict__ Alo,
                                                const __half* __restrict__ Bt,
                                                int K, int m0, int n0, int kt,
                                                uint32_t sbase, int tid) {
#pragma unroll
    for (int i = 0; i < 2; i++) {
        int c = tid + i * 256;
        int r = c >> 2, c16 = c & 3;
        uint32_t off = (uint32_t)(r * APB + c16 * 16);
        size_t ga = (size_t)(m0 + r) * K + kt * 32 + c16 * 8;
        size_t gb = (size_t)(n0 + r) * K + kt * 32 + c16 * 8;
        CP_ASYNC16(sbase + off,              Ahi + ga);
        CP_ASYNC16(sbase + A_SB + off,       Alo + ga);
        CP_ASYNC16(sbase + 2 * A_SB + off,   Bt + gb);
    }
    CP_COMMIT();
}

__global__ void __launch_bounds__(256, 2) gemm_f16_kernel(const __half* __restrict__ Ahi,
                                                          const __half* __restrict__ Alo,
                                                          const __half* __restrict__ Bt,
                                                          float* __restrict__ C,
                                                          int N, int K) {
    extern __shared__ char smraw[];
    uint32_t sm_b = smem_u32(smraw);
    const int tid = threadIdx.x;
    const int wid = tid >> 5;
    const int lane = tid & 31;
    const int warpM = wid & 1;
    const int warpN = wid >> 1;
    const int m0 = blockIdx.y * GBM;
    const int n0 = blockIdx.x * GBN;
    const int NT = K / 32;
    const int lr = lane >> 2;
    const int lc = lane & 3;
    const int lm_row = lane & 15;
    const int lm_hi  = (lane >> 4) * 16;

    float acc[4][4][4];
#pragma unroll
    for (int i = 0; i < 4; i++)
#pragma unroll
        for (int j = 0; j < 4; j++)
#pragma unroll
            for (int u = 0; u < 4; u++) acc[i][j][u] = 0.0f;

    gemm_stage_load(Ahi, Alo, Bt, K, m0, n0, 0, sm_b, tid);

    for (int kt = 0; kt < NT; kt++) {
        CP_WAIT0();
        __syncthreads();
        if (kt + 1 < NT)
            gemm_stage_load(Ahi, Alo, Bt, K, m0, n0, kt + 1,
                            sm_b + (uint32_t)(((kt + 1) & 1) * STAGE_B), tid);

        uint32_t sA = sm_b + (uint32_t)((kt & 1) * STAGE_B);
        uint32_t a_base = sA + (uint32_t)((warpM * 64 + lm_row) * APB + lm_hi);
        uint32_t b_base = sA + 2u * A_SB + (uint32_t)((warpN * 32 + lm_row) * APB + lm_hi);

#pragma unroll
        for (int half = 0; half < 2; half++) {
            uint32_t hb = (uint32_t)(half * 32);
            uint32_t bh[2][4];
#pragma unroll
            for (int nb = 0; nb < 2; nb++)
                LDMX4(bh[nb], b_base + (uint32_t)(nb * 16 * APB) + hb);
#pragma unroll
            for (int ma = 0; ma < 4; ma++) {
                uint32_t ah[4], al[4];
                uint32_t addr = a_base + (uint32_t)(ma * 16 * APB) + hb;
                LDMX4(ah, addr);
                LDMX4(al, addr + A_SB);
#pragma unroll
                for (int na = 0; na < 4; na++) {
                    int nb = na >> 1, j = na & 1;
                    mma_f16(acc[ma][na], ah, bh[nb][j], bh[nb][j + 2]);
                    mma_f16(acc[ma][na], al, bh[nb][j], bh[nb][j + 2]);
                }
            }
        }
    }

#pragma unroll
    for (int ma = 0; ma < 4; ma++) {
        int r0 = m0 + warpM * 64 + ma * 16 + lr;
#pragma unroll
        for (int na = 0; na < 4; na++) {
            int c0 = n0 + warpN * 32 + na * 8 + lc * 2;
            *(float2*)(C + (size_t)r0 * N + c0)       = make_float2(acc[ma][na][0], acc[ma][na][1]);
            *(float2*)(C + (size_t)(r0 + 8) * N + c0) = make_float2(acc[ma][na][2], acc[ma][na][3]);
        }
    }
}

// ================= pre-kernels =================
__global__ void splitx_f16_kernel(const float* __restrict__ x,
                                  __half* __restrict__ xhi,
                                  __half* __restrict__ xlo, int n4) {
    int i = blockIdx.x * blockDim.x + threadIdx.x;
    if (i < n4) {
        float4 v = ((const float4*)x)[i];
        float f[4] = {v.x, v.y, v.z, v.w};
        __half h[4], l[4];
#pragma unroll
        for (int j = 0; j < 4; j++) {
            h[j] = __float2half_rn(f[j]);
            l[j] = __float2half_rn(f[j] - __half2float(h[j]));
        }
        ((uint2*)xhi)[i] = *(uint2*)h;
        ((uint2*)xlo)[i] = *(uint2*)l;
    }
}

// transpose + round f16: W[K][Nc] fp32 -> WT[(nrow_off + n)][K] f16
__global__ void wt_f16_kernel(const float* __restrict__ W,
                              __half* __restrict__ WT,
                              int K, int Nc, int nrow_off) {
    __shared__ float tile[32][33];
    int n0 = blockIdx.x * 32, k0 = blockIdx.y * 32;
    int tx = threadIdx.x, ty = threadIdx.y;
#pragma unroll
    for (int i = 0; i < 4; i++)
        tile[ty + i * 8][tx] = W[(size_t)(k0 + ty + i * 8) * Nc + n0 + tx];
    __syncthreads();
#pragma unroll
    for (int i = 0; i < 4; i++) {
        float v = tile[tx][ty + i * 8];
        WT[(size_t)(nrow_off + n0 + ty + i * 8) * K + k0 + tx] = __float2half_rn(v);
    }
}

// ---------------- prep: rmsnorm(q,k) + RoPE ----------------
__global__ void prep_kernel() {
    int t = blockIdx.x, h = blockIdx.y, b = blockIdx.z;
    int d = threadIdx.x;
    const float* p = g_C + ((size_t)(b * T_ + t)) * CN + h * 384;
    float qv = p[d], kv = p[128 + d], vv = p[256 + d];

    __shared__ float redq[4], redk[4];
    __shared__ float qs[128], ks[128];
    float q2 = qv * qv, k2 = kv * kv;
#pragma unroll
    for (int off = 16; off > 0; off >>= 1) {
        q2 += __shfl_xor_sync(0xffffffffu, q2, off);
        k2 += __shfl_xor_sync(0xffffffffu, k2, off);
    }
    if ((d & 31) == 0) { redq[d >> 5] = q2; redk[d >> 5] = k2; }
    __syncthreads();
    float sq = redq[0] + redq[1] + redq[2] + redq[3];
    float sk = redk[0] + redk[1] + redk[2] + redk[3];
    float qn = qv * rsqrtf(sq * (1.0f / 128.0f) + 1e-6f);
    float kn = kv * rsqrtf(sk * (1.0f / 128.0f) + 1e-6f);
    qs[d] = qn; ks[d] = kn;
    __syncthreads();

    int dd = d & 63;
    float freq = (float)t * expf(-(float)dd * (9.210340371976184f / 64.0f));
    float c = cosf(freq), s = sinf(freq);
    float qr, kr;
    if (d < 64) { qr =  qs[d] * c + qs[d + 64] * s;  kr =  ks[d] * c + ks[d + 64] * s; }
    else        { qr = -qs[dd] * s + qs[d] * c;      kr = -ks[dd] * s + ks[d] * c;     }

    const float QSCL = 0.08838834764831845f * 1.44269504088896340f;
    size_t qi = ((size_t)(b * NH + h) * T_ + t) * HD + d;
    g_Q[qi] = qr * QSCL;
    float krr; CVT_TF32(krr, kr);
    g_K[qi] = krr;
    float vvr; CVT_TF32(vvr, vv);
    size_t vi = ((size_t)(b * HP_ + (h >> 1)) * T_ + t) * 256 + (size_t)(h & 1) * 128 + d;
    g_V[vi] = vvr;
}

// ---------------- V transpose ----------------
__global__ void vtrans_kernel() {
    __shared__ float tile[32][33];
    int t0 = blockIdx.x * 32, e0 = blockIdx.y * 32, bhp = blockIdx.z;
    const float* src = g_V + (size_t)bhp * T_ * 256;
    float* dst = g_Vt + (size_t)bhp * 256 * T_;
    int tx = threadIdx.x, ty = threadIdx.y;
#pragma unroll
    for (int i = 0; i < 4; i++)
        tile[ty + i * 8][tx] = src[(size_t)(t0 + ty + i * 8) * 256 + e0 + tx];
    __syncthreads();
#pragma unroll
    for (int i = 0; i < 4; i++)
        dst[(size_t)(e0 + ty + i * 8) * T_ + t0 + tx] = tile[tx][ty + i * 8];
}

// ---------------- lambda ----------------
__global__ void lam_kernel(const float* __restrict__ lq1, const float* __restrict__ lk1,
                           const float* __restrict__ lq2, const float* __restrict__ lk2) {
    int hp = threadIdx.y;
    int lane = threadIdx.x;
    float s1 = lq1[hp*64 + lane] * lk1[hp*64 + lane] + lq1[hp*64 + lane + 32] * lk1[hp*64 + lane + 32];
    float s2 = lq2[hp*64 + lane] * lk2[hp*64 + lane] + lq2[hp*64 + lane + 32] * lk2[hp*64 + lane + 32];
#pragma unroll
    for (int off = 16; off > 0; off >>= 1) {
        s1 += __shfl_xor_sync(0xffffffffu, s1, off);
        s2 += __shfl_xor_sync(0xffffffffu, s2, off);
    }
    if (lane == 0) g_lam[hp] = expf(s1) - expf(s2) + LAMBDA_INIT;
}

// ---------------- flash attention, tf32 mma, single-Q (unchanged from R7) ----------------
#define QP 132
#define KTP 132
#define VTP 76
#define PP 68
#define OFF_QS  0
#define OFF_KS0 (OFF_QS + 64 * QP)
#define OFF_KS1 (OFF_KS0 + 64 * KTP)
#define OFF_VT  (OFF_KS1 + 64 * KTP)
#define OFF_PS  (OFF_VT + 256 * VTP)
#define OFF_WMAX (OFF_PS + 64 * PP)
#define OFF_WSUM (OFF_WMAX + 128)
#define ATT_SMEM ((OFF_WSUM + 128) * 4)

__global__ void __launch_bounds__(256, 1) attn_kernel() {
    const int mt = gridDim.x - 1 - blockIdx.x;
    const int h = blockIdx.y, b = blockIdx.z;
    const int tid = threadIdx.x, wid = tid >> 5, lane = tid & 31;
    const int wM = wid & 3, wN = wid >> 2;
    const int lr = lane >> 2, lc = lane & 3;
    const int r0 = wM * 16 + lr;
    const int x_row = ((lane >> 3) & 1) * 8 + (lane & 7);
    const int x_col = (lane >> 4) * 4;

    extern __shared__ float sm[];
    uint32_t smb = smem_u32(sm);
    float* Ps = sm + OFF_PS;
    float* wmaxs = sm + OFF_WMAX;
    float* wsums = sm + OFF_WSUM;

    const float* Qg  = g_Q  + ((size_t)(b * NH + h) * T_ + (size_t)mt * 64) * HD;
    const float* Kg  = g_K  + (size_t)(b * NH + h) * T_ * HD;
    const float* Vtg = g_Vt + (size_t)(b * HP_ + (h >> 1)) * 256 * T_;
    float*       Yg  = g_Y  + (size_t)(b * NH + h) * T_ * 256;

#pragma unroll
    for (int i = 0; i < 8; i++) {
        int idx = tid + i * 256;
        int r = idx >> 5, c4 = (idx & 31) * 4;
        CP_ASYNC16(smb + (uint32_t)(OFF_KS0 + r * KTP + c4) * 4u,
                   Kg + (size_t)r * HD + c4);
    }
    CP_COMMIT();

    for (int c = tid; c < 64 * 32; c += 256) {
        int q = c >> 5, d4 = (c & 31) * 4;
        float4 v = *(const float4*)(Qg + (size_t)q * HD + d4);
        CVT_TF32(v.x, v.x); CVT_TF32(v.y, v.y);
        CVT_TF32(v.z, v.z); CVT_TF32(v.w, v.w);
        *(float4*)(sm + OFF_QS + q * QP + d4) = v;
    }

    float O[16][4];
#pragma unroll
    for (int i = 0; i < 16; i++)
#pragma unroll
        for (int j = 0; j < 4; j++) O[i][j] = 0.0f;
    float m0 = -1e30f, m1 = -1e30f, l0 = 0.0f, l1 = 0.0f;

    const uint32_t qs_base  = smb + (uint32_t)(OFF_QS + (wM * 16 + x_row) * QP + x_col) * 4u;
    const uint32_t ps_base  = smb + (uint32_t)(OFF_PS + (wM * 16 + x_row) * PP + x_col) * 4u;
    const uint32_t vt_base  = smb + (uint32_t)(OFF_VT + (wN * 128 + x_row) * VTP + x_col) * 4u;
    const uint32_t ks_base0 = smb + (uint32_t)(OFF_KS0 + (wN * 32 + x_row) * KTP + x_col) * 4u;
    const uint32_t ks_base1 = smb + (uint32_t)(OFF_KS1 + (wN * 32 + x_row) * KTP + x_col) * 4u;

    for (int nt = 0; nt <= mt; nt++) {
        __syncthreads();
#pragma unroll
        for (int i = 0; i < 16; i++) {
            int idx = tid + i * 256;
            int r = idx >> 4, c4 = (idx & 15) * 4;
            CP_ASYNC16(smb + (uint32_t)(OFF_VT + r * VTP + c4) * 4u,
                       Vtg + (size_t)r * T_ + nt * 64 + c4);
        }
        CP_COMMIT();
        if (nt < mt) {
            int koff = ((nt + 1) & 1) ? OFF_KS1 : OFF_KS0;
#pragma unroll
            for (int i = 0; i < 8; i++) {
                int idx = tid + i * 256;
                int r = idx >> 5, c4 = (idx & 31) * 4;
                CP_ASYNC16(smb + (uint32_t)(koff + r * KTP + c4) * 4u,
                           Kg + (size_t)((nt + 1) * 64 + r) * HD + c4);
            }
            CP_COMMIT();
        }
        if (nt < mt) { CP_WAIT2(); } else { CP_WAIT1(); }
        __syncthreads();

        uint32_t kb_base = (nt & 1) ? ks_base1 : ks_base0;
        float accS[4][4];
#pragma unroll
        for (int na = 0; na < 4; na++)
#pragma unroll
            for (int u = 0; u < 4; u++) accS[na][u] = 0.0f;
#pragma unroll 4
        for (int ks = 0; ks < 16; ks++) {
            uint32_t ah[4];
            LDMX4(ah, qs_base + ks * 32u);
#pragma unroll
            for (int pr = 0; pr < 2; pr++) {
                uint32_t kb[4];
                LDMX4(kb, kb_base + (uint32_t)(pr * 16 * KTP) * 4u + ks * 32u);
                mma_tf32(accS[pr * 2],     ah, kb[0], kb[2]);
                mma_tf32(accS[pr * 2 + 1], ah, kb[1], kb[3]);
            }
        }

        if (nt == mt) {
#pragma unroll
            for (int na = 0; na < 4; na++) {
                int col = wN * 32 + na * 8 + 2 * lc;
                if (col     > r0)     accS[na][0] = -1e30f;
                if (col + 1 > r0)     accS[na][1] = -1e30f;
                if (col     > r0 + 8) accS[na][2] = -1e30f;
                if (col + 1 > r0 + 8) accS[na][3] = -1e30f;
            }
        }

        float mx0 = -1e30f, mx1 = -1e30f;
#pragma unroll
        for (int na = 0; na < 4; na++) {
            mx0 = fmaxf(mx0, fmaxf(accS[na][0], accS[na][1]));
            mx1 = fmaxf(mx1, fmaxf(accS[na][2], accS[na][3]));
        }
        mx0 = fmaxf(mx0, __shfl_xor_sync(0xffffffffu, mx0, 1));
        mx0 = fmaxf(mx0, __shfl_xor_sync(0xffffffffu, mx0, 2));
        mx1 = fmaxf(mx1, __shfl_xor_sync(0xffffffffu, mx1, 1));
        mx1 = fmaxf(mx1, __shfl_xor_sync(0xffffffffu, mx1, 2));
        if ((lane & 3) == 0) {
            wmaxs[wN * 64 + r0]     = mx0;
            wmaxs[wN * 64 + r0 + 8] = mx1;
        }
        __syncthreads();
        float mn0 = fmaxf(m0, fmaxf(wmaxs[r0], wmaxs[64 + r0]));
        float mn1 = fmaxf(m1, fmaxf(wmaxs[r0 + 8], wmaxs[64 + r0 + 8]));
        float a0, a1;
        EX2F(a0, m0 - mn0);
        EX2F(a1, m1 - mn1);
        float s0 = 0.0f, s1 = 0.0f;
#pragma unroll
        for (int na = 0; na < 4; na++) {
            float p00, p01, p10, p11;
            EX2F(p00, accS[na][0] - mn0);
            EX2F(p01, accS[na][1] - mn0);
            EX2F(p10, accS[na][2] - mn1);
            EX2F(p11, accS[na][3] - mn1);
            CVT_TF32(p00, p00); CVT_TF32(p01, p01);
            CVT_TF32(p10, p10); CVT_TF32(p11, p11);
            s0 += p00 + p01; s1 += p10 + p11;
            int col = wN * 32 + na * 8 + 2 * lc;
            *(float2*)(Ps + r0 * PP + col)       = make_float2(p00, p01);
            *(float2*)(Ps + (r0 + 8) * PP + col) = make_float2(p10, p11);
        }
        s0 += __shfl_xor_sync(0xffffffffu, s0, 1);
        s0 += __shfl_xor_sync(0xffffffffu, s0, 2);
        s1 += __shfl_xor_sync(0xffffffffu, s1, 1);
        s1 += __shfl_xor_sync(0xffffffffu, s1, 2);
        if ((lane & 3) == 0) {
            wsums[wN * 64 + r0]     = s0;
            wsums[wN * 64 + r0 + 8] = s1;
        }
        if (nt < mt) { CP_WAIT1(); } else { CP_WAIT0(); }
        __syncthreads();
        l0 = l0 * a0 + wsums[r0] + wsums[64 + r0];
        l1 = l1 * a1 + wsums[r0 + 8] + wsums[64 + r0 + 8];
        m0 = mn0; m1 = mn1;
#pragma unroll
        for (int i = 0; i < 16; i++) {
            O[i][0] *= a0; O[i][1] *= a0; O[i][2] *= a1; O[i][3] *= a1;
        }

#pragma unroll 2
        for (int ks = 0; ks < 8; ks++) {
            uint32_t pf[4];
            LDMX4(pf, ps_base + ks * 32u);
#pragma unroll
            for (int pr = 0; pr < 8; pr++) {
                uint32_t vb[4];
                LDMX4(vb, vt_base + (uint32_t)(pr * 16 * VTP) * 4u + ks * 32u);
                mma_tf32(O[pr * 2],     pf, vb[0], vb[2]);
                mma_tf32(O[pr * 2 + 1], pf, vb[1], vb[3]);
            }
        }
    }

    float i0, i1;
    asm("rcp.approx.f32 %0, %1;" : "=f"(i0) : "f"(l0));
    asm("rcp.approx.f32 %0, %1;" : "=f"(i1) : "f"(l1));
    int tg0 = mt * 64 + r0;
#pragma unroll
    for (int na = 0; na < 16; na++) {
        int col = wN * 128 + na * 8 + 2 * lc;
        *(float2*)(Yg + (size_t)tg0 * 256 + col)       = make_float2(O[na][0] * i0, O[na][1] * i0);
        *(float2*)(Yg + (size_t)(tg0 + 8) * 256 + col) = make_float2(O[na][2] * i1, O[na][3] * i1);
    }
}

// ---------------- combine ----------------
__global__ void combine_kernel(float* __restrict__ out) {
    int t = blockIdx.x, hp = blockIdx.y, b = blockIdx.z;
    int e = threadIdx.x;
    size_t y1i = ((size_t)(b * NH + 2 * hp)     * T_ + t) * 256 + e;
    size_t y2i = ((size_t)(b * NH + 2 * hp + 1) * T_ + t) * 256 + e;
    float y1 = g_Y[y1i], y2 = g_Y[y2i];
    float lam = g_lam[hp];
    float gv = g_C[((size_t)(b * T_ + t)) * CN + QKV_N + hp * 256 + e];
    float sg = gv / (1.0f + expf(-gv));
    float yv = (y1 - lam * y2) * sg;

    __shared__ float red[8];
    float s = yv * yv;
#pragma unroll
    for (int off = 16; off > 0; off >>= 1)
        s += __shfl_xor_sync(0xffffffffu, s, off);
    if ((e & 31) == 0) red[e >> 5] = s;
    __syncthreads();
    float tot = 0.0f;
#pragma unroll
    for (int w = 0; w < 8; w++) tot += red[w];
    float r = rsqrtf(tot * (1.0f / 256.0f) + 1e-6f) * ONE_MINUS_LI;
    out[((size_t)(b * T_ + t)) * DM + hp * 256 + e] = yv * r;
}

// ---------------- launch ----------------
extern "C" void kernel_launch(void* const* d_in, const int* in_sizes, int n_in,
                              void* d_out, int out_size) {
    const float* x    = (const float*)d_in[0];
    const float* Wqkv = (const float*)d_in[1];
    const float* lq1  = (const float*)d_in[2];
    const float* lk1  = (const float*)d_in[3];
    const float* lq2  = (const float*)d_in[4];
    const float* lk2  = (const float*)d_in[5];
    const float* Wg   = (const float*)d_in[6];
    float* out = (float*)d_out;

    float *c_p;
    __half *xhi_p, *xlo_p, *wt_p;
    cudaGetSymbolAddress((void**)&c_p,   g_C);
    cudaGetSymbolAddress((void**)&xhi_p, g_Xhi);
    cudaGetSymbolAddress((void**)&xlo_p, g_Xlo);
    cudaGetSymbolAddress((void**)&wt_p,  g_WT);

    // 0) split x (f16 hi/lo), transpose+round weights into fused [8192][2048] f16
    int nx4 = B_ * T_ * DM / 4;
    splitx_f16_kernel<<<(nx4 + 255) / 256, 256>>>(x, xhi_p, xlo_p, nx4);
    wt_f16_kernel<<<dim3(QKV_N / 32, DM / 32), dim3(32, 8)>>>(Wqkv, wt_p, DM, QKV_N, 0);
    wt_f16_kernel<<<dim3(DM / 32,    DM / 32), dim3(32, 8)>>>(Wg,   wt_p, DM, DM, QKV_N);

    // 1) fused projection GEMM: C[4096][8192] = x @ [Wqkv | Wg]
    cudaFuncSetAttribute(gemm_f16_kernel, cudaFuncAttributeMaxDynamicSharedMemorySize, GEMM_SMEM);
    gemm_f16_kernel<<<dim3(CN / GBN, (B_ * T_) / GBM), 256, GEMM_SMEM>>>(xhi_p, xlo_p, wt_p, c_p, CN, DM);

    // 2) rmsnorm + rope
    prep_kernel<<<dim3(T_, NH, B_), 128>>>();
    // 3) V transpose
    vtrans_kernel<<<dim3(T_ / 32, 256 / 32, B_ * HP_), dim3(32, 8)>>>();
    // 4) lambda
    lam_kernel<<<1, dim3(32, 8)>>>(lq1, lk1, lq2, lk2);
    // 5) attention
    cudaFuncSetAttribute(attn_kernel, cudaFuncAttributeMaxDynamicSharedMemorySize, ATT_SMEM);
    attn_kernel<<<dim3(T_ / 64, NH, B_), 256, ATT_SMEM>>>();
    // 6) combine
    combine_kernel<<<dim3(T_, HP_, B_), 256>>>(out);
}

// round 9
// speedup vs baseline: 1.7851x; 1.2129x over previous
#include <cuda_runtime.h>
#include <cuda_fp16.h>
#include <math.h>
#include <cstdint>

#define B_   2
#define T_   2048
#define DM   2048
#define NH   16
#define HD   128
#define HP_  8
#define QKV_N 6144
#define CN   8192
#define LAMBDA_INIT  0.7008206670670481f
#define ONE_MINUS_LI 0.2991793329329519f

// ---------------- scratch ----------------
__device__ float g_C[(size_t)B_ * T_ * CN];
__device__ __half g_Qh[(size_t)B_ * NH * T_ * HD];
__device__ __half g_Kh[(size_t)B_ * NH * T_ * HD];
__device__ __half g_Vh[(size_t)B_ * HP_ * T_ * 256];
__device__ __half g_Vth[(size_t)B_ * HP_ * 256 * T_];
__device__ float g_Y[(size_t)B_ * NH * T_ * 256];
__device__ float g_lam[HP_];
__device__ __half g_Xhi[(size_t)B_ * T_ * DM];
__device__ __half g_Xlo[(size_t)B_ * T_ * DM];
__device__ __half g_WT[(size_t)CN * DM];

// ================= helpers =================
__device__ __forceinline__ uint32_t smem_u32(const void* p) {
    uint32_t a;
    asm("{ .reg .u64 t; cvta.to.shared.u64 t, %1; cvt.u32.u64 %0, t; }" : "=r"(a) : "l"(p));
    return a;
}
#define CP_ASYNC16(dst, src) \
    asm volatile("cp.async.cg.shared.global [%0], [%1], 16;" :: "r"(dst), "l"(src) : "memory")
#define CP_COMMIT() asm volatile("cp.async.commit_group;" ::: "memory")
#define CP_WAIT0()  asm volatile("cp.async.wait_group 0;" ::: "memory")
#define CP_WAIT1()  asm volatile("cp.async.wait_group 1;" ::: "memory")
#define CP_WAIT2()  asm volatile("cp.async.wait_group 2;" ::: "memory")
#define EX2F(d, s)     asm("ex2.approx.f32 %0, %1;" : "=f"(d) : "f"(s))
#define LDMX4(r, addr) \
    asm volatile("ldmatrix.sync.aligned.m8n8.x4.shared.b16 {%0,%1,%2,%3}, [%4];" \
        : "=r"((r)[0]), "=r"((r)[1]), "=r"((r)[2]), "=r"((r)[3]) : "r"(addr))

__device__ __forceinline__ void mma_f16(float* c, const uint32_t* a, uint32_t b0, uint32_t b1) {
    asm volatile(
        "mma.sync.aligned.m16n8k16.row.col.f32.f16.f16.f32 "
        "{%0,%1,%2,%3}, {%4,%5,%6,%7}, {%8,%9}, {%0,%1,%2,%3};"
        : "+f"(c[0]), "+f"(c[1]), "+f"(c[2]), "+f"(c[3])
        : "r"(a[0]), "r"(a[1]), "r"(a[2]), "r"(a[3]), "r"(b0), "r"(b1));
}

// ================= f16 split-A GEMM (unchanged from R8) =================
#define GBM 128
#define GBN 128
#define APB 80
#define A_SB (128 * APB)
#define STAGE_B (3 * A_SB)
#define GEMM_SMEM (2 * STAGE_B)

__device__ __forceinline__ void gemm_stage_load(const __half* __restrict__ Ahi,
                                                const __half* __restrict__ Alo,
                                                const __half* __restrict__ Bt,
                                                int K, int m0, int n0, int kt,
                                                uint32_t sbase, int tid) {
#pragma unroll
    for (int i = 0; i < 2; i++) {
        int c = tid + i * 256;
        int r = c >> 2, c16 = c & 3;
        uint32_t off = (uint32_t)(r * APB + c16 * 16);
        size_t ga = (size_t)(m0 + r) * K + kt * 32 + c16 * 8;
        size_t gb = (size_t)(n0 + r) * K + kt * 32 + c16 * 8;
        CP_ASYNC16(sbase + off,              Ahi + ga);
        CP_ASYNC16(sbase + A_SB + off,       Alo + ga);
        CP_ASYNC16(sbase + 2 * A_SB + off,   Bt + gb);
    }
    CP_COMMIT();
}

__global__ void __launch_bounds__(256, 2) gemm_f16_kernel(const __half* __restrict__ Ahi,
                                                          const __half* __restrict__ Alo,
                                                          const __half* __restrict__ Bt,
                                                          float* __restrict__ C,
                                                          int N, int K) {
    extern __shared__ char smraw[];
    uint32_t sm_b = smem_u32(smraw);
    const int tid = threadIdx.x;
    const int wid = tid >> 5;
    const int lane = tid & 31;
    const int warpM = wid & 1;
    const int warpN = wid >> 1;
    const int m0 = blockIdx.y * GBM;
    const int n0 = blockIdx.x * GBN;
    const int NT = K / 32;
    const int lr = lane >> 2;
    const int lc = lane & 3;
    const int lm_row = lane & 15;
    const int lm_hi  = (lane >> 4) * 16;

    float acc[4][4][4];
#pragma unroll
    for (int i = 0; i < 4; i++)
#pragma unroll
        for (int j = 0; j < 4; j++)
#pragma unroll
            for (int u = 0; u < 4; u++) acc[i][j][u] = 0.0f;

    gemm_stage_load(Ahi, Alo, Bt, K, m0, n0, 0, sm_b, tid);

    for (int kt = 0; kt < NT; kt++) {
        CP_WAIT0();
        __syncthreads();
        if (kt + 1 < NT)
            gemm_stage_load(Ahi, Alo, Bt, K, m0, n0, kt + 1,
                            sm_b + (uint32_t)(((kt + 1) & 1) * STAGE_B), tid);

        uint32_t sA = sm_b + (uint32_t)((kt & 1) * STAGE_B);
        uint32_t a_base = sA + (uint32_t)((warpM * 64 + lm_row) * APB + lm_hi);
        uint32_t b_base = sA + 2u * A_SB + (uint32_t)((warpN * 32 + lm_row) * APB + lm_hi);

#pragma unroll
        for (int half = 0; half < 2; half++) {
            uint32_t hb = (uint32_t)(half * 32);
            uint32_t bh[2][4];
#pragma unroll
            for (int nb = 0; nb < 2; nb++)
                LDMX4(bh[nb], b_base + (uint32_t)(nb * 16 * APB) + hb);
#pragma unroll
            for (int ma = 0; ma < 4; ma++) {
                uint32_t ah[4], al[4];
                uint32_t addr = a_base + (uint32_t)(ma * 16 * APB) + hb;
                LDMX4(ah, addr);
                LDMX4(al, addr + A_SB);
#pragma unroll
                for (int na = 0; na < 4; na++) {
                    int nb = na >> 1, j = na & 1;
                    mma_f16(acc[ma][na], ah, bh[nb][j], bh[nb][j + 2]);
                    mma_f16(acc[ma][na], al, bh[nb][j], bh[nb][j + 2]);
                }
            }
        }
    }

#pragma unroll
    for (int ma = 0; ma < 4; ma++) {
        int r0 = m0 + warpM * 64 + ma * 16 + lr;
#pragma unroll
        for (int na = 0; na < 4; na++) {
            int c0 = n0 + warpN * 32 + na * 8 + lc * 2;
            *(float2*)(C + (size_t)r0 * N + c0)       = make_float2(acc[ma][na][0], acc[ma][na][1]);
            *(float2*)(C + (size_t)(r0 + 8) * N + c0) = make_float2(acc[ma][na][2], acc[ma][na][3]);
        }
    }
}

// ================= pre-kernels =================
__global__ void splitx_f16_kernel(const float* __restrict__ x,
                                  __half* __restrict__ xhi,
                                  __half* __restrict__ xlo, int n4) {
    int i = blockIdx.x * blockDim.x + threadIdx.x;
    if (i < n4) {
        float4 v = ((const float4*)x)[i];
        float f[4] = {v.x, v.y, v.z, v.w};
        __half h[4], l[4];
#pragma unroll
        for (int j = 0; j < 4; j++) {
            h[j] = __float2half_rn(f[j]);
            l[j] = __float2half_rn(f[j] - __half2float(h[j]));
        }
        ((uint2*)xhi)[i] = *(uint2*)h;
        ((uint2*)xlo)[i] = *(uint2*)l;
    }
}

__global__ void wt_f16_kernel(const float* __restrict__ W,
                              __half* __restrict__ WT,
                              int K, int Nc, int nrow_off) {
    __shared__ float tile[32][33];
    int n0 = blockIdx.x * 32, k0 = blockIdx.y * 32;
    int tx = threadIdx.x, ty = threadIdx.y;
#pragma unroll
    for (int i = 0; i < 4; i++)
        tile[ty + i * 8][tx] = W[(size_t)(k0 + ty + i * 8) * Nc + n0 + tx];
    __syncthreads();
#pragma unroll
    for (int i = 0; i < 4; i++) {
        float v = tile[tx][ty + i * 8];
        WT[(size_t)(nrow_off + n0 + ty + i * 8) * K + k0 + tx] = __float2half_rn(v);
    }
}

// ---------------- prep: rmsnorm(q,k) + RoPE -> f16 ----------------
__global__ void prep_kernel() {
    int t = blockIdx.x, h = blockIdx.y, b = blockIdx.z;
    int d = threadIdx.x;
    const float* p = g_C + ((size_t)(b * T_ + t)) * CN + h * 384;
    float qv = p[d], kv = p[128 + d], vv = p[256 + d];

    __shared__ float redq[4], redk[4];
    __shared__ float qs[128], ks[128];
    float q2 = qv * qv, k2 = kv * kv;
#pragma unroll
    for (int off = 16; off > 0; off >>= 1) {
        q2 += __shfl_xor_sync(0xffffffffu, q2, off);
        k2 += __shfl_xor_sync(0xffffffffu, k2, off);
    }
    if ((d & 31) == 0) { redq[d >> 5] = q2; redk[d >> 5] = k2; }
    __syncthreads();
    float sq = redq[0] + redq[1] + redq[2] + redq[3];
    float sk = redk[0] + redk[1] + redk[2] + redk[3];
    float qn = qv * rsqrtf(sq * (1.0f / 128.0f) + 1e-6f);
    float kn = kv * rsqrtf(sk * (1.0f / 128.0f) + 1e-6f);
    qs[d] = qn; ks[d] = kn;
    __syncthreads();

    int dd = d & 63;
    float freq = (float)t * expf(-(float)dd * (9.210340371976184f / 64.0f));
    float c = cosf(freq), s = sinf(freq);
    float qr, kr;
    if (d < 64) { qr =  qs[d] * c + qs[d + 64] * s;  kr =  ks[d] * c + ks[d + 64] * s; }
    else        { qr = -qs[dd] * s + qs[d] * c;      kr = -ks[dd] * s + ks[d] * c;     }

    const float QSCL = 0.08838834764831845f * 1.44269504088896340f;
    size_t qi = ((size_t)(b * NH + h) * T_ + t) * HD + d;
    g_Qh[qi] = __float2half_rn(qr * QSCL);
    g_Kh[qi] = __float2half_rn(kr);
    size_t vi = ((size_t)(b * HP_ + (h >> 1)) * T_ + t) * 256 + (size_t)(h & 1) * 128 + d;
    g_Vh[vi] = __float2half_rn(vv);
}

// ---------------- V transpose (f16) ----------------
__global__ void vtrans_kernel() {
    __shared__ __half tile[32][34];
    int t0 = blockIdx.x * 32, e0 = blockIdx.y * 32, bhp = blockIdx.z;
    const __half* src = g_Vh + (size_t)bhp * T_ * 256;
    __half* dst = g_Vth + (size_t)bhp * 256 * T_;
    int tx = threadIdx.x, ty = threadIdx.y;
#pragma unroll
    for (int i = 0; i < 4; i++)
        tile[ty + i * 8][tx] = src[(size_t)(t0 + ty + i * 8) * 256 + e0 + tx];
    __syncthreads();
#pragma unroll
    for (int i = 0; i < 4; i++)
        dst[(size_t)(e0 + ty + i * 8) * T_ + t0 + tx] = tile[tx][ty + i * 8];
}

// ---------------- lambda ----------------
__global__ void lam_kernel(const float* __restrict__ lq1, const float* __restrict__ lk1,
                           const float* __restrict__ lq2, const float* __restrict__ lk2) {
    int hp = threadIdx.y;
    int lane = threadIdx.x;
    float s1 = lq1[hp*64 + lane] * lk1[hp*64 + lane] + lq1[hp*64 + lane + 32] * lk1[hp*64 + lane + 32];
    float s2 = lq2[hp*64 + lane] * lk2[hp*64 + lane] + lq2[hp*64 + lane + 32] * lk2[hp*64 + lane + 32];
#pragma unroll
    for (int off = 16; off > 0; off >>= 1) {
        s1 += __shfl_xor_sync(0xffffffffu, s1, off);
        s2 += __shfl_xor_sync(0xffffffffu, s2, off);
    }
    if (lane == 0) g_lam[hp] = expf(s1) - expf(s2) + LAMBDA_INIT;
}

// ---------------- flash attention, f16 mma ----------------
// byte offsets; Q/K pitch 272B (128 f16 + pad), V/P pitch 144B (64/72 f16)
#define QS_B   0
#define KS0_B  17408
#define KS1_B  34816
#define VT_B   52224
#define PS_B   89088
#define WMAX_B 98304
#define WSUM_B 98816
#define ATT_SMEM 99328

__global__ void __launch_bounds__(256, 2) attn_kernel() {
    const int mt = gridDim.x - 1 - blockIdx.x;
    const int h = blockIdx.y, b = blockIdx.z;
    const int tid = threadIdx.x, wid = tid >> 5, lane = tid & 31;
    const int wM = wid & 3, wN = wid >> 2;
    const int lr = lane >> 2, lc = lane & 3;
    const int r0 = wM * 16 + lr;
    const int lm_row = lane & 15;
    const int lm_hi  = (lane >> 4) * 16;

    extern __shared__ char smc[];
    uint32_t smb = smem_u32(smc);
    float* wmaxs = (float*)(smc + WMAX_B);
    float* wsums = (float*)(smc + WSUM_B);

    const __half* Qg  = g_Qh  + ((size_t)(b * NH + h) * T_ + (size_t)mt * 64) * HD;
    const __half* Kg  = g_Kh  + (size_t)(b * NH + h) * T_ * HD;
    const __half* Vtg = g_Vth + (size_t)(b * HP_ + (h >> 1)) * 256 * T_;
    float*        Yg  = g_Y   + (size_t)(b * NH + h) * T_ * 256;

    // prologue: K(0) tile [64t][128d], then Q tile [64q][128d]
#pragma unroll
    for (int i = 0; i < 4; i++) {
        int idx = tid + i * 256;
        int r = idx >> 4, c16 = idx & 15;
        CP_ASYNC16(smb + (uint32_t)(KS0_B + r * 272 + c16 * 16),
                   Kg + (size_t)r * HD + c16 * 8);
    }
    CP_COMMIT();
#pragma unroll
    for (int i = 0; i < 4; i++) {
        int idx = tid + i * 256;
        int r = idx >> 4, c16 = idx & 15;
        CP_ASYNC16(smb + (uint32_t)(QS_B + r * 272 + c16 * 16),
                   Qg + (size_t)r * HD + c16 * 8);
    }
    CP_COMMIT();

    float O[16][4];
#pragma unroll
    for (int i = 0; i < 16; i++)
#pragma unroll
        for (int j = 0; j < 4; j++) O[i][j] = 0.0f;
    float m0 = -1e30f, m1 = -1e30f, l0 = 0.0f, l1 = 0.0f;

    const uint32_t qs_base  = smb + (uint32_t)(QS_B  + (wM * 16 + lm_row) * 272 + lm_hi);
    const uint32_t ks_base0 = smb + (uint32_t)(KS0_B + (wN * 32 + lm_row) * 272 + lm_hi);
    const uint32_t ks_base1 = smb + (uint32_t)(KS1_B + (wN * 32 + lm_row) * 272 + lm_hi);
    const uint32_t ps_base  = smb + (uint32_t)(PS_B  + (wM * 16 + lm_row) * 144 + lm_hi);
    const uint32_t vt_base  = smb + (uint32_t)(VT_B  + (wN * 128 + lm_row) * 144 + lm_hi);

    for (int nt = 0; nt <= mt; nt++) {
        __syncthreads();
        // V(nt): [256e][64t] f16
#pragma unroll
        for (int i = 0; i < 8; i++) {
            int idx = tid + i * 256;
            int r = idx >> 3, c = idx & 7;
            CP_ASYNC16(smb + (uint32_t)(VT_B + r * 144 + c * 16),
                       Vtg + (size_t)r * T_ + nt * 64 + c * 8);
        }
        CP_COMMIT();
        // prefetch K(nt+1)
        if (nt < mt) {
            int koff = ((nt + 1) & 1) ? KS1_B : KS0_B;
#pragma unroll
            for (int i = 0; i < 4; i++) {
                int idx = tid + i * 256;
                int r = idx >> 4, c16 = idx & 15;
                CP_ASYNC16(smb + (uint32_t)(koff + r * 272 + c16 * 16),
                           Kg + (size_t)((nt + 1) * 64 + r) * HD + c16 * 8);
            }
            CP_COMMIT();
        }
        if (nt < mt) { CP_WAIT2(); } else { CP_WAIT1(); }
        __syncthreads();

        // ---- S = Q K^T (f16 m16n8k16) ----
        uint32_t kb_base = (nt & 1) ? ks_base1 : ks_base0;
        float accS[4][4];
#pragma unroll
        for (int na = 0; na < 4; na++)
#pragma unroll
            for (int u = 0; u < 4; u++) accS[na][u] = 0.0f;
#pragma unroll 4
        for (int ks = 0; ks < 8; ks++) {
            uint32_t ah[4];
            LDMX4(ah, qs_base + ks * 32u);
#pragma unroll
            for (int pr = 0; pr < 2; pr++) {
                uint32_t kb[4];
                LDMX4(kb, kb_base + (uint32_t)(pr * 16 * 272) + ks * 32u);
                mma_f16(accS[pr * 2],     ah, kb[0], kb[2]);
                mma_f16(accS[pr * 2 + 1], ah, kb[1], kb[3]);
            }
        }

        // ---- causal mask ----
        if (nt == mt) {
#pragma unroll
            for (int na = 0; na < 4; na++) {
                int col = wN * 32 + na * 8 + 2 * lc;
                if (col     > r0)     accS[na][0] = -1e30f;
                if (col + 1 > r0)     accS[na][1] = -1e30f;
                if (col     > r0 + 8) accS[na][2] = -1e30f;
                if (col + 1 > r0 + 8) accS[na][3] = -1e30f;
            }
        }

        // ---- online softmax ----
        float mx0 = -1e30f, mx1 = -1e30f;
#pragma unroll
        for (int na = 0; na < 4; na++) {
            mx0 = fmaxf(mx0, fmaxf(accS[na][0], accS[na][1]));
            mx1 = fmaxf(mx1, fmaxf(accS[na][2], accS[na][3]));
        }
        mx0 = fmaxf(mx0, __shfl_xor_sync(0xffffffffu, mx0, 1));
        mx0 = fmaxf(mx0, __shfl_xor_sync(0xffffffffu, mx0, 2));
        mx1 = fmaxf(mx1, __shfl_xor_sync(0xffffffffu, mx1, 1));
        mx1 = fmaxf(mx1, __shfl_xor_sync(0xffffffffu, mx1, 2));
        if ((lane & 3) == 0) {
            wmaxs[wN * 64 + r0]     = mx0;
            wmaxs[wN * 64 + r0 + 8] = mx1;
        }
        __syncthreads();
        float mn0 = fmaxf(m0, fmaxf(wmaxs[r0], wmaxs[64 + r0]));
        float mn1 = fmaxf(m1, fmaxf(wmaxs[r0 + 8], wmaxs[64 + r0 + 8]));
        float a0, a1;
        EX2F(a0, m0 - mn0);
        EX2F(a1, m1 - mn1);
        float s0 = 0.0f, s1 = 0.0f;
#pragma unroll
        for (int na = 0; na < 4; na++) {
            float p00, p01, p10, p11;
            EX2F(p00, accS[na][0] - mn0);
            EX2F(p01, accS[na][1] - mn0);
            EX2F(p10, accS[na][2] - mn1);
            EX2F(p11, accS[na][3] - mn1);
            __half hp00 = __float2half_rn(p00), hp01 = __float2half_rn(p01);
            __half hp10 = __float2half_rn(p10), hp11 = __float2half_rn(p11);
            s0 += __half2float(hp00) + __half2float(hp01);
            s1 += __half2float(hp10) + __half2float(hp11);
            int col = wN * 32 + na * 8 + 2 * lc;
            *(__half2*)(smc + PS_B + r0 * 144 + col * 2)       = __halves2half2(hp00, hp01);
            *(__half2*)(smc + PS_B + (r0 + 8) * 144 + col * 2) = __halves2half2(hp10, hp11);
        }
        s0 += __shfl_xor_sync(0xffffffffu, s0, 1);
        s0 += __shfl_xor_sync(0xffffffffu, s0, 2);
        s1 += __shfl_xor_sync(0xffffffffu, s1, 1);
        s1 += __shfl_xor_sync(0xffffffffu, s1, 2);
        if ((lane & 3) == 0) {
            wsums[wN * 64 + r0]     = s0;
            wsums[wN * 64 + r0 + 8] = s1;
        }
        if (nt < mt) { CP_WAIT1(); } else { CP_WAIT0(); }
        __syncthreads();
        l0 = l0 * a0 + wsums[r0] + wsums[64 + r0];
        l1 = l1 * a1 + wsums[r0 + 8] + wsums[64 + r0 + 8];
        m0 = mn0; m1 = mn1;
#pragma unroll
        for (int i = 0; i < 16; i++) {
            O[i][0] *= a0; O[i][1] *= a0; O[i][2] *= a1; O[i][3] *= a1;
        }

        // ---- O += P @ V (f16 m16n8k16) ----
#pragma unroll 2
        for (int ks = 0; ks < 4; ks++) {
            uint32_t pf[4];
            LDMX4(pf, ps_base + ks * 32u);
#pragma unroll
            for (int pr = 0; pr < 8; pr++) {
                uint32_t vb[4];
                LDMX4(vb, vt_base + (uint32_t)(pr * 16 * 144) + ks * 32u);
                mma_f16(O[pr * 2],     pf, vb[0], vb[2]);
                mma_f16(O[pr * 2 + 1], pf, vb[1], vb[3]);
            }
        }
    }

    float i0, i1;
    asm("rcp.approx.f32 %0, %1;" : "=f"(i0) : "f"(l0));
    asm("rcp.approx.f32 %0, %1;" : "=f"(i1) : "f"(l1));
    int tg0 = mt * 64 + r0;
#pragma unroll
    for (int na = 0; na < 16; na++) {
        int col = wN * 128 + na * 8 + 2 * lc;
        *(float2*)(Yg + (size_t)tg0 * 256 + col)       = make_float2(O[na][0] * i0, O[na][1] * i0);
        *(float2*)(Yg + (size_t)(tg0 + 8) * 256 + col) = make_float2(O[na][2] * i1, O[na][3] * i1);
    }
}

// ---------------- combine ----------------
__global__ void combine_kernel(float* __restrict__ out) {
    int t = blockIdx.x, hp = blockIdx.y, b = blockIdx.z;
    int e = threadIdx.x;
    size_t y1i = ((size_t)(b * NH + 2 * hp)     * T_ + t) * 256 + e;
    size_t y2i = ((size_t)(b * NH + 2 * hp + 1) * T_ + t) * 256 + e;
    float y1 = g_Y[y1i], y2 = g_Y[y2i];
    float lam = g_lam[hp];
    float gv = g_C[((size_t)(b * T_ + t)) * CN + QKV_N + hp * 256 + e];
    float sg = gv / (1.0f + expf(-gv));
    float yv = (y1 - lam * y2) * sg;

    __shared__ float red[8];
    float s = yv * yv;
#pragma unroll
    for (int off = 16; off > 0; off >>= 1)
        s += __shfl_xor_sync(0xffffffffu, s, off);
    if ((e & 31) == 0) red[e >> 5] = s;
    __syncthreads();
    float tot = 0.0f;
#pragma unroll
    for (int w = 0; w < 8; w++) tot += red[w];
    float r = rsqrtf(tot * (1.0f / 256.0f) + 1e-6f) * ONE_MINUS_LI;
    out[((size_t)(b * T_ + t)) * DM + hp * 256 + e] = yv * r;
}

// ---------------- launch ----------------
extern "C" void kernel_launch(void* const* d_in, const int* in_sizes, int n_in,
                              void* d_out, int out_size) {
    const float* x    = (const float*)d_in[0];
    const float* Wqkv = (const float*)d_in[1];
    const float* lq1  = (const float*)d_in[2];
    const float* lk1  = (const float*)d_in[3];
    const float* lq2  = (const float*)d_in[4];
    const float* lk2  = (const float*)d_in[5];
    const float* Wg   = (const float*)d_in[6];
    float* out = (float*)d_out;

    float *c_p;
    __half *xhi_p, *xlo_p, *wt_p;
    cudaGetSymbolAddress((void**)&c_p,   g_C);
    cudaGetSymbolAddress((void**)&xhi_p, g_Xhi);
    cudaGetSymbolAddress((void**)&xlo_p, g_Xlo);
    cudaGetSymbolAddress((void**)&wt_p,  g_WT);

    int nx4 = B_ * T_ * DM / 4;
    splitx_f16_kernel<<<(nx4 + 255) / 256, 256>>>(x, xhi_p, xlo_p, nx4);
    wt_f16_kernel<<<dim3(QKV_N / 32, DM / 32), dim3(32, 8)>>>(Wqkv, wt_p, DM, QKV_N, 0);
    wt_f16_kernel<<<dim3(DM / 32,    DM / 32), dim3(32, 8)>>>(Wg,   wt_p, DM, DM, QKV_N);

    cudaFuncSetAttribute(gemm_f16_kernel, cudaFuncAttributeMaxDynamicSharedMemorySize, GEMM_SMEM);
    gemm_f16_kernel<<<dim3(CN / GBN, (B_ * T_) / GBM), 256, GEMM_SMEM>>>(xhi_p, xlo_p, wt_p, c_p, CN, DM);

    prep_kernel<<<dim3(T_, NH, B_), 128>>>();
    vtrans_kernel<<<dim3(T_ / 32, 256 / 32, B_ * HP_), dim3(32, 8)>>>();
    lam_kernel<<<1, dim3(32, 8)>>>(lq1, lk1, lq2, lk2);
    cudaFuncSetAttribute(attn_kernel, cudaFuncAttributeMaxDynamicSharedMemorySize, ATT_SMEM);
    attn_kernel<<<dim3(T_ / 64, NH, B_), 256, ATT_SMEM>>>();
    combine_kernel<<<dim3(T_, HP_, B_), 256>>>(out);
}

// round 10
// speedup vs baseline: 1.9950x; 1.1176x over previous
#include <cuda_runtime.h>
#include <cuda_fp16.h>
#include <math.h>
#include <cstdint>

#define B_   2
#define T_   2048
#define DM   2048
#define NH   16
#define HD   128
#define HP_  8
#define QKV_N 6144
#define CN   8192
#define LAMBDA_INIT  0.7008206670670481f
#define ONE_MINUS_LI 0.2991793329329519f

// ---------------- scratch ----------------
__device__ float g_C[(size_t)B_ * T_ * CN];
__device__ __half g_Qh[(size_t)B_ * NH * T_ * HD];
__device__ __half g_Kh[(size_t)B_ * NH * T_ * HD];
__device__ __half g_Vh[(size_t)B_ * HP_ * T_ * 256];
__device__ __half g_Vth[(size_t)B_ * HP_ * 256 * T_];
__device__ float g_Y[(size_t)B_ * NH * T_ * 256];
__device__ float g_lam[HP_];
__device__ __half g_Xhi[(size_t)B_ * T_ * DM];
__device__ __half g_Xlo[(size_t)B_ * T_ * DM];
__device__ __half g_WT[(size_t)CN * DM];

// ================= helpers =================
__device__ __forceinline__ uint32_t smem_u32(const void* p) {
    uint32_t a;
    asm("{ .reg .u64 t; cvta.to.shared.u64 t, %1; cvt.u32.u64 %0, t; }" : "=r"(a) : "l"(p));
    return a;
}
#define CP_ASYNC16(dst, src) \
    asm volatile("cp.async.cg.shared.global [%0], [%1], 16;" :: "r"(dst), "l"(src) : "memory")
#define CP_COMMIT() asm volatile("cp.async.commit_group;" ::: "memory")
#define CP_WAIT0()  asm volatile("cp.async.wait_group 0;" ::: "memory")
#define CP_WAIT1()  asm volatile("cp.async.wait_group 1;" ::: "memory")
#define CP_WAIT2()  asm volatile("cp.async.wait_group 2;" ::: "memory")
#define EX2F(d, s)     asm("ex2.approx.f32 %0, %1;" : "=f"(d) : "f"(s))
#define LDMX4(r, addr) \
    asm volatile("ldmatrix.sync.aligned.m8n8.x4.shared.b16 {%0,%1,%2,%3}, [%4];" \
        : "=r"((r)[0]), "=r"((r)[1]), "=r"((r)[2]), "=r"((r)[3]) : "r"(addr))

__device__ __forceinline__ void mma_f16(float* c, const uint32_t* a, uint32_t b0, uint32_t b1) {
    asm volatile(
        "mma.sync.aligned.m16n8k16.row.col.f32.f16.f16.f32 "
        "{%0,%1,%2,%3}, {%4,%5,%6,%7}, {%8,%9}, {%0,%1,%2,%3};"
        : "+f"(c[0]), "+f"(c[1]), "+f"(c[2]), "+f"(c[3])
        : "r"(a[0]), "r"(a[1]), "r"(a[2]), "r"(a[3]), "r"(b0), "r"(b1));
}

// ================= f16 GEMM: qkv cols single-mma, gate cols split-A =================
#define GBM 128
#define GBN 128
#define APB 80
#define A_SB (128 * APB)
#define STAGE_B (3 * A_SB)
#define GEMM_SMEM (2 * STAGE_B)

__device__ __forceinline__ void gemm_stage_load(const __half* __restrict__ Ahi,
                                                const __half* __restrict__ Alo,
                                                const __half* __restrict__ Bt,
                                                int K, int m0, int n0, int kt,
                                                uint32_t sbase, int tid, bool lo) {
#pragma unroll
    for (int i = 0; i < 2; i++) {
        int c = tid + i * 256;
        int r = c >> 2, c16 = c & 3;
        uint32_t off = (uint32_t)(r * APB + c16 * 16);
        size_t ga = (size_t)(m0 + r) * K + kt * 32 + c16 * 8;
        size_t gb = (size_t)(n0 + r) * K + kt * 32 + c16 * 8;
        CP_ASYNC16(sbase + off,              Ahi + ga);
        if (lo) CP_ASYNC16(sbase + A_SB + off, Alo + ga);
        CP_ASYNC16(sbase + 2 * A_SB + off,   Bt + gb);
    }
    CP_COMMIT();
}

__global__ void __launch_bounds__(256, 2) gemm_f16_kernel(const __half* __restrict__ Ahi,
                                                          const __half* __restrict__ Alo,
                                                          const __half* __restrict__ Bt,
                                                          float* __restrict__ C,
                                                          int N, int K) {
    extern __shared__ char smraw[];
    uint32_t sm_b = smem_u32(smraw);
    const int tid = threadIdx.x;
    const int wid = tid >> 5;
    const int lane = tid & 31;
    const int warpM = wid & 1;
    const int warpN = wid >> 1;
    const int m0 = blockIdx.y * GBM;
    const int n0 = blockIdx.x * GBN;
    const bool lo = (n0 >= QKV_N);   // gate columns: exact split-A; qkv columns: single f16
    const int NT = K / 32;
    const int lr = lane >> 2;
    const int lc = lane & 3;
    const int lm_row = lane & 15;
    const int lm_hi  = (lane >> 4) * 16;

    float acc[4][4][4];
#pragma unroll
    for (int i = 0; i < 4; i++)
#pragma unroll
        for (int j = 0; j < 4; j++)
#pragma unroll
            for (int u = 0; u < 4; u++) acc[i][j][u] = 0.0f;

    gemm_stage_load(Ahi, Alo, Bt, K, m0, n0, 0, sm_b, tid, lo);

    for (int kt = 0; kt < NT; kt++) {
        CP_WAIT0();
        __syncthreads();
        if (kt + 1 < NT)
            gemm_stage_load(Ahi, Alo, Bt, K, m0, n0, kt + 1,
                            sm_b + (uint32_t)(((kt + 1) & 1) * STAGE_B), tid, lo);

        uint32_t sA = sm_b + (uint32_t)((kt & 1) * STAGE_B);
        uint32_t a_base = sA + (uint32_t)((warpM * 64 + lm_row) * APB + lm_hi);
        uint32_t b_base = sA + 2u * A_SB + (uint32_t)((warpN * 32 + lm_row) * APB + lm_hi);

#pragma unroll
        for (int half = 0; half < 2; half++) {
            uint32_t hb = (uint32_t)(half * 32);
            uint32_t bh[2][4];
#pragma unroll
            for (int nb = 0; nb < 2; nb++)
                LDMX4(bh[nb], b_base + (uint32_t)(nb * 16 * APB) + hb);
#pragma unroll
            for (int ma = 0; ma < 4; ma++) {
                uint32_t ah[4], al[4];
                uint32_t addr = a_base + (uint32_t)(ma * 16 * APB) + hb;
                LDMX4(ah, addr);
                if (lo) LDMX4(al, addr + A_SB);
#pragma unroll
                for (int na = 0; na < 4; na++) {
                    int nb = na >> 1, j = na & 1;
                    mma_f16(acc[ma][na], ah, bh[nb][j], bh[nb][j + 2]);
                    if (lo) mma_f16(acc[ma][na], al, bh[nb][j], bh[nb][j + 2]);
                }
            }
        }
    }

#pragma unroll
    for (int ma = 0; ma < 4; ma++) {
        int r0 = m0 + warpM * 64 + ma * 16 + lr;
#pragma unroll
        for (int na = 0; na < 4; na++) {
            int c0 = n0 + warpN * 32 + na * 8 + lc * 2;
            *(float2*)(C + (size_t)r0 * N + c0)       = make_float2(acc[ma][na][0], acc[ma][na][1]);
            *(float2*)(C + (size_t)(r0 + 8) * N + c0) = make_float2(acc[ma][na][2], acc[ma][na][3]);
        }
    }
}

// ================= pre-kernels =================
__global__ void splitx_f16_kernel(const float* __restrict__ x,
                                  __half* __restrict__ xhi,
                                  __half* __restrict__ xlo, int n4) {
    int i = blockIdx.x * blockDim.x + threadIdx.x;
    if (i < n4) {
        float4 v = ((const float4*)x)[i];
        float f[4] = {v.x, v.y, v.z, v.w};
        __half h[4], l[4];
#pragma unroll
        for (int j = 0; j < 4; j++) {
            h[j] = __float2half_rn(f[j]);
            l[j] = __float2half_rn(f[j] - __half2float(h[j]));
        }
        ((uint2*)xhi)[i] = *(uint2*)h;
        ((uint2*)xlo)[i] = *(uint2*)l;
    }
}

__global__ void wt_f16_kernel(const float* __restrict__ W,
                              __half* __restrict__ WT,
                              int K, int Nc, int nrow_off) {
    __shared__ float tile[32][33];
    int n0 = blockIdx.x * 32, k0 = blockIdx.y * 32;
    int tx = threadIdx.x, ty = threadIdx.y;
#pragma unroll
    for (int i = 0; i < 4; i++)
        tile[ty + i * 8][tx] = W[(size_t)(k0 + ty + i * 8) * Nc + n0 + tx];
    __syncthreads();
#pragma unroll
    for (int i = 0; i < 4; i++) {
        float v = tile[tx][ty + i * 8];
        WT[(size_t)(nrow_off + n0 + ty + i * 8) * K + k0 + tx] = __float2half_rn(v);
    }
}

// ---------------- prep: rmsnorm(q,k) + RoPE -> f16 ----------------
__global__ void prep_kernel() {
    int t = blockIdx.x, h = blockIdx.y, b = blockIdx.z;
    int d = threadIdx.x;
    const float* p = g_C + ((size_t)(b * T_ + t)) * CN + h * 384;
    float qv = p[d], kv = p[128 + d], vv = p[256 + d];

    __shared__ float redq[4], redk[4];
    __shared__ float qs[128], ks[128];
    float q2 = qv * qv, k2 = kv * kv;
#pragma unroll
    for (int off = 16; off > 0; off >>= 1) {
        q2 += __shfl_xor_sync(0xffffffffu, q2, off);
        k2 += __shfl_xor_sync(0xffffffffu, k2, off);
    }
    if ((d & 31) == 0) { redq[d >> 5] = q2; redk[d >> 5] = k2; }
    __syncthreads();
    float sq = redq[0] + redq[1] + redq[2] + redq[3];
    float sk = redk[0] + redk[1] + redk[2] + redk[3];
    float qn = qv * rsqrtf(sq * (1.0f / 128.0f) + 1e-6f);
    float kn = kv * rsqrtf(sk * (1.0f / 128.0f) + 1e-6f);
    qs[d] = qn; ks[d] = kn;
    __syncthreads();

    int dd = d & 63;
    float freq = (float)t * expf(-(float)dd * (9.210340371976184f / 64.0f));
    float c = cosf(freq), s = sinf(freq);
    float qr, kr;
    if (d < 64) { qr =  qs[d] * c + qs[d + 64] * s;  kr =  ks[d] * c + ks[d + 64] * s; }
    else        { qr = -qs[dd] * s + qs[d] * c;      kr = -ks[dd] * s + ks[d] * c;     }

    const float QSCL = 0.08838834764831845f * 1.44269504088896340f;
    size_t qi = ((size_t)(b * NH + h) * T_ + t) * HD + d;
    g_Qh[qi] = __float2half_rn(qr * QSCL);
    g_Kh[qi] = __float2half_rn(kr);
    size_t vi = ((size_t)(b * HP_ + (h >> 1)) * T_ + t) * 256 + (size_t)(h & 1) * 128 + d;
    g_Vh[vi] = __float2half_rn(vv);
}

// ---------------- V transpose (f16) ----------------
__global__ void vtrans_kernel() {
    __shared__ __half tile[32][34];
    int t0 = blockIdx.x * 32, e0 = blockIdx.y * 32, bhp = blockIdx.z;
    const __half* src = g_Vh + (size_t)bhp * T_ * 256;
    __half* dst = g_Vth + (size_t)bhp * 256 * T_;
    int tx = threadIdx.x, ty = threadIdx.y;
#pragma unroll
    for (int i = 0; i < 4; i++)
        tile[ty + i * 8][tx] = src[(size_t)(t0 + ty + i * 8) * 256 + e0 + tx];
    __syncthreads();
#pragma unroll
    for (int i = 0; i < 4; i++)
        dst[(size_t)(e0 + ty + i * 8) * T_ + t0 + tx] = tile[tx][ty + i * 8];
}

// ---------------- lambda ----------------
__global__ void lam_kernel(const float* __restrict__ lq1, const float* __restrict__ lk1,
                           const float* __restrict__ lq2, const float* __restrict__ lk2) {
    int hp = threadIdx.y;
    int lane = threadIdx.x;
    float s1 = lq1[hp*64 + lane] * lk1[hp*64 + lane] + lq1[hp*64 + lane + 32] * lk1[hp*64 + lane + 32];
    float s2 = lq2[hp*64 + lane] * lk2[hp*64 + lane] + lq2[hp*64 + lane + 32] * lk2[hp*64 + lane + 32];
#pragma unroll
    for (int off = 16; off > 0; off >>= 1) {
        s1 += __shfl_xor_sync(0xffffffffu, s1, off);
        s2 += __shfl_xor_sync(0xffffffffu, s2, off);
    }
    if (lane == 0) g_lam[hp] = expf(s1) - expf(s2) + LAMBDA_INIT;
}

// ---------------- flash attention, f16 mma (unchanged from R9) ----------------
#define QS_B   0
#define KS0_B  17408
#define KS1_B  34816
#define VT_B   52224
#define PS_B   89088
#define WMAX_B 98304
#define WSUM_B 98816
#define ATT_SMEM 99328

__global__ void __launch_bounds__(256, 2) attn_kernel() {
    const int mt = gridDim.x - 1 - blockIdx.x;
    const int h = blockIdx.y, b = blockIdx.z;
    const int tid = threadIdx.x, wid = tid >> 5, lane = tid & 31;
    const int wM = wid & 3, wN = wid >> 2;
    const int lr = lane >> 2, lc = lane & 3;
    const int r0 = wM * 16 + lr;
    const int lm_row = lane & 15;
    const int lm_hi  = (lane >> 4) * 16;

    extern __shared__ char smc[];
    uint32_t smb = smem_u32(smc);
    float* wmaxs = (float*)(smc + WMAX_B);
    float* wsums = (float*)(smc + WSUM_B);

    const __half* Qg  = g_Qh  + ((size_t)(b * NH + h) * T_ + (size_t)mt * 64) * HD;
    const __half* Kg  = g_Kh  + (size_t)(b * NH + h) * T_ * HD;
    const __half* Vtg = g_Vth + (size_t)(b * HP_ + (h >> 1)) * 256 * T_;
    float*        Yg  = g_Y   + (size_t)(b * NH + h) * T_ * 256;

#pragma unroll
    for (int i = 0; i < 4; i++) {
        int idx = tid + i * 256;
        int r = idx >> 4, c16 = idx & 15;
        CP_ASYNC16(smb + (uint32_t)(KS0_B + r * 272 + c16 * 16),
                   Kg + (size_t)r * HD + c16 * 8);
    }
    CP_COMMIT();
#pragma unroll
    for (int i = 0; i < 4; i++) {
        int idx = tid + i * 256;
        int r = idx >> 4, c16 = idx & 15;
        CP_ASYNC16(smb + (uint32_t)(QS_B + r * 272 + c16 * 16),
                   Qg + (size_t)r * HD + c16 * 8);
    }
    CP_COMMIT();

    float O[16][4];
#pragma unroll
    for (int i = 0; i < 16; i++)
#pragma unroll
        for (int j = 0; j < 4; j++) O[i][j] = 0.0f;
    float m0 = -1e30f, m1 = -1e30f, l0 = 0.0f, l1 = 0.0f;

    const uint32_t qs_base  = smb + (uint32_t)(QS_B  + (wM * 16 + lm_row) * 272 + lm_hi);
    const uint32_t ks_base0 = smb + (uint32_t)(KS0_B + (wN * 32 + lm_row) * 272 + lm_hi);
    const uint32_t ks_base1 = smb + (uint32_t)(KS1_B + (wN * 32 + lm_row) * 272 + lm_hi);
    const uint32_t ps_base  = smb + (uint32_t)(PS_B  + (wM * 16 + lm_row) * 144 + lm_hi);
    const uint32_t vt_base  = smb + (uint32_t)(VT_B  + (wN * 128 + lm_row) * 144 + lm_hi);

    for (int nt = 0; nt <= mt; nt++) {
        __syncthreads();
#pragma unroll
        for (int i = 0; i < 8; i++) {
            int idx = tid + i * 256;
            int r = idx >> 3, c = idx & 7;
            CP_ASYNC16(smb + (uint32_t)(VT_B + r * 144 + c * 16),
                       Vtg + (size_t)r * T_ + nt * 64 + c * 8);
        }
        CP_COMMIT();
        if (nt < mt) {
            int koff = ((nt + 1) & 1) ? KS1_B : KS0_B;
#pragma unroll
            for (int i = 0; i < 4; i++) {
                int idx = tid + i * 256;
                int r = idx >> 4, c16 = idx & 15;
                CP_ASYNC16(smb + (uint32_t)(koff + r * 272 + c16 * 16),
                           Kg + (size_t)((nt + 1) * 64 + r) * HD + c16 * 8);
            }
            CP_COMMIT();
        }
        if (nt < mt) { CP_WAIT2(); } else { CP_WAIT1(); }
        __syncthreads();

        uint32_t kb_base = (nt & 1) ? ks_base1 : ks_base0;
        float accS[4][4];
#pragma unroll
        for (int na = 0; na < 4; na++)
#pragma unroll
            for (int u = 0; u < 4; u++) accS[na][u] = 0.0f;
#pragma unroll 4
        for (int ks = 0; ks < 8; ks++) {
            uint32_t ah[4];
            LDMX4(ah, qs_base + ks * 32u);
#pragma unroll
            for (int pr = 0; pr < 2; pr++) {
                uint32_t kb[4];
                LDMX4(kb, kb_base + (uint32_t)(pr * 16 * 272) + ks * 32u);
                mma_f16(accS[pr * 2],     ah, kb[0], kb[2]);
                mma_f16(accS[pr * 2 + 1], ah, kb[1], kb[3]);
            }
        }

        if (nt == mt) {
#pragma unroll
            for (int na = 0; na < 4; na++) {
                int col = wN * 32 + na * 8 + 2 * lc;
                if (col     > r0)     accS[na][0] = -1e30f;
                if (col + 1 > r0)     accS[na][1] = -1e30f;
                if (col     > r0 + 8) accS[na][2] = -1e30f;
                if (col + 1 > r0 + 8) accS[na][3] = -1e30f;
            }
        }

        float mx0 = -1e30f, mx1 = -1e30f;
#pragma unroll
        for (int na = 0; na < 4; na++) {
            mx0 = fmaxf(mx0, fmaxf(accS[na][0], accS[na][1]));
            mx1 = fmaxf(mx1, fmaxf(accS[na][2], accS[na][3]));
        }
        mx0 = fmaxf(mx0, __shfl_xor_sync(0xffffffffu, mx0, 1));
        mx0 = fmaxf(mx0, __shfl_xor_sync(0xffffffffu, mx0, 2));
        mx1 = fmaxf(mx1, __shfl_xor_sync(0xffffffffu, mx1, 1));
        mx1 = fmaxf(mx1, __shfl_xor_sync(0xffffffffu, mx1, 2));
        if ((lane & 3) == 0) {
            wmaxs[wN * 64 + r0]     = mx0;
            wmaxs[wN * 64 + r0 + 8] = mx1;
        }
        __syncthreads();
        float mn0 = fmaxf(m0, fmaxf(wmaxs[r0], wmaxs[64 + r0]));
        float mn1 = fmaxf(m1, fmaxf(wmaxs[r0 + 8], wmaxs[64 + r0 + 8]));
        float a0, a1;
        EX2F(a0, m0 - mn0);
        EX2F(a1, m1 - mn1);
        float s0 = 0.0f, s1 = 0.0f;
#pragma unroll
        for (int na = 0; na < 4; na++) {
            float p00, p01, p10, p11;
            EX2F(p00, accS[na][0] - mn0);
            EX2F(p01, accS[na][1] - mn0);
            EX2F(p10, accS[na][2] - mn1);
            EX2F(p11, accS[na][3] - mn1);
            __half hp00 = __float2half_rn(p00), hp01 = __float2half_rn(p01);
            __half hp10 = __float2half_rn(p10), hp11 = __float2half_rn(p11);
            s0 += __half2float(hp00) + __half2float(hp01);
            s1 += __half2float(hp10) + __half2float(hp11);
            int col = wN * 32 + na * 8 + 2 * lc;
            *(__half2*)(smc + PS_B + r0 * 144 + col * 2)       = __halves2half2(hp00, hp01);
            *(__half2*)(smc + PS_B + (r0 + 8) * 144 + col * 2) = __halves2half2(hp10, hp11);
        }
        s0 += __shfl_xor_sync(0xffffffffu, s0, 1);
        s0 += __shfl_xor_sync(0xffffffffu, s0, 2);
        s1 += __shfl_xor_sync(0xffffffffu, s1, 1);
        s1 += __shfl_xor_sync(0xffffffffu, s1, 2);
        if ((lane & 3) == 0) {
            wsums[wN * 64 + r0]     = s0;
            wsums[wN * 64 + r0 + 8] = s1;
        }
        if (nt < mt) { CP_WAIT1(); } else { CP_WAIT0(); }
        __syncthreads();
        l0 = l0 * a0 + wsums[r0] + wsums[64 + r0];
        l1 = l1 * a1 + wsums[r0 + 8] + wsums[64 + r0 + 8];
        m0 = mn0; m1 = mn1;
#pragma unroll
        for (int i = 0; i < 16; i++) {
            O[i][0] *= a0; O[i][1] *= a0; O[i][2] *= a1; O[i][3] *= a1;
        }

#pragma unroll 2
        for (int ks = 0; ks < 4; ks++) {
            uint32_t pf[4];
            LDMX4(pf, ps_base + ks * 32u);
#pragma unroll
            for (int pr = 0; pr < 8; pr++) {
                uint32_t vb[4];
                LDMX4(vb, vt_base + (uint32_t)(pr * 16 * 144) + ks * 32u);
                mma_f16(O[pr * 2],     pf, vb[0], vb[2]);
                mma_f16(O[pr * 2 + 1], pf, vb[1], vb[3]);
            }
        }
    }

    float i0, i1;
    asm("rcp.approx.f32 %0, %1;" : "=f"(i0) : "f"(l0));
    asm("rcp.approx.f32 %0, %1;" : "=f"(i1) : "f"(l1));
    int tg0 = mt * 64 + r0;
#pragma unroll
    for (int na = 0; na < 16; na++) {
        int col = wN * 128 + na * 8 + 2 * lc;
        *(float2*)(Yg + (size_t)tg0 * 256 + col)       = make_float2(O[na][0] * i0, O[na][1] * i0);
        *(float2*)(Yg + (size_t)(tg0 + 8) * 256 + col) = make_float2(O[na][2] * i1, O[na][3] * i1);
    }
}

// ---------------- combine ----------------
__global__ void combine_kernel(float* __restrict__ out) {
    int t = blockIdx.x, hp = blockIdx.y, b = blockIdx.z;
    int e = threadIdx.x;
    size_t y1i = ((size_t)(b * NH + 2 * hp)     * T_ + t) * 256 + e;
    size_t y2i = ((size_t)(b * NH + 2 * hp + 1) * T_ + t) * 256 + e;
    float y1 = g_Y[y1i], y2 = g_Y[y2i];
    float lam = g_lam[hp];
    float gv = g_C[((size_t)(b * T_ + t)) * CN + QKV_N + hp * 256 + e];
    float sg = gv / (1.0f + expf(-gv));
    float yv = (y1 - lam * y2) * sg;

    __shared__ float red[8];
    float s = yv * yv;
#pragma unroll
    for (int off = 16; off > 0; off >>= 1)
        s += __shfl_xor_sync(0xffffffffu, s, off);
    if ((e & 31) == 0) red[e >> 5] = s;
    __syncthreads();
    float tot = 0.0f;
#pragma unroll
    for (int w = 0; w < 8; w++) tot += red[w];
    float r = rsqrtf(tot * (1.0f / 256.0f) + 1e-6f) * ONE_MINUS_LI;
    out[((size_t)(b * T_ + t)) * DM + hp * 256 + e] = yv * r;
}

// ---------------- launch ----------------
extern "C" void kernel_launch(void* const* d_in, const int* in_sizes, int n_in,
                              void* d_out, int out_size) {
    const float* x    = (const float*)d_in[0];
    const float* Wqkv = (const float*)d_in[1];
    const float* lq1  = (const float*)d_in[2];
    const float* lk1  = (const float*)d_in[3];
    const float* lq2  = (const float*)d_in[4];
    const float* lk2  = (const float*)d_in[5];
    const float* Wg   = (const float*)d_in[6];
    float* out = (float*)d_out;

    float *c_p;
    __half *xhi_p, *xlo_p, *wt_p;
    cudaGetSymbolAddress((void**)&c_p,   g_C);
    cudaGetSymbolAddress((void**)&xhi_p, g_Xhi);
    cudaGetSymbolAddress((void**)&xlo_p, g_Xlo);
    cudaGetSymbolAddress((void**)&wt_p,  g_WT);

    int nx4 = B_ * T_ * DM / 4;
    splitx_f16_kernel<<<(nx4 + 255) / 256, 256>>>(x, xhi_p, xlo_p, nx4);
    wt_f16_kernel<<<dim3(QKV_N / 32, DM / 32), dim3(32, 8)>>>(Wqkv, wt_p, DM, QKV_N, 0);
    wt_f16_kernel<<<dim3(DM / 32,    DM / 32), dim3(32, 8)>>>(Wg,   wt_p, DM, DM, QKV_N);

    cudaFuncSetAttribute(gemm_f16_kernel, cudaFuncAttributeMaxDynamicSharedMemorySize, GEMM_SMEM);
    gemm_f16_kernel<<<dim3(CN / GBN, (B_ * T_) / GBM), 256, GEMM_SMEM>>>(xhi_p, xlo_p, wt_p, c_p, CN, DM);

    prep_kernel<<<dim3(T_, NH, B_), 128>>>();
    vtrans_kernel<<<dim3(T_ / 32, 256 / 32, B_ * HP_), dim3(32, 8)>>>();
    lam_kernel<<<1, dim3(32, 8)>>>(lq1, lk1, lq2, lk2);
    cudaFuncSetAttribute(attn_kernel, cudaFuncAttributeMaxDynamicSharedMemorySize, ATT_SMEM);
    attn_kernel<<<dim3(T_ / 64, NH, B_), 256, ATT_SMEM>>>();
    combine_kernel<<<dim3(T_, HP_, B_), 256>>>(out);
}

// round 11
// speedup vs baseline: 2.0048x; 1.0049x over previous
#include <cuda_runtime.h>
#include <cuda_fp16.h>
#include <math.h>
#include <cstdint>

#define B_   2
#define T_   2048
#define DM   2048
#define NH   16
#define HD   128
#define HP_  8
#define QKV_N 6144
#define CN   8192
#define LAMBDA_INIT  0.7008206670670481f
#define ONE_MINUS_LI 0.2991793329329519f

// ---------------- scratch ----------------
__device__ float g_C[(size_t)B_ * T_ * CN];
__device__ __half g_Qh[(size_t)B_ * NH * T_ * HD];
__device__ __half g_Kh[(size_t)B_ * NH * T_ * HD];
__device__ __half g_Vh[(size_t)B_ * HP_ * T_ * 256];
__device__ __half g_Vth[(size_t)B_ * HP_ * 256 * T_];
__device__ float g_Y[(size_t)B_ * NH * T_ * 256];
__device__ float g_lam[HP_];
__device__ __half g_Xhi[(size_t)B_ * T_ * DM];
__device__ __half g_Xlo[(size_t)B_ * T_ * DM];
__device__ __half g_WT[(size_t)CN * DM];

// ================= helpers =================
__device__ __forceinline__ uint32_t smem_u32(const void* p) {
    uint32_t a;
    asm("{ .reg .u64 t; cvta.to.shared.u64 t, %1; cvt.u32.u64 %0, t; }" : "=r"(a) : "l"(p));
    return a;
}
#define CP_ASYNC16(dst, src) \
    asm volatile("cp.async.cg.shared.global [%0], [%1], 16;" :: "r"(dst), "l"(src) : "memory")
#define CP_COMMIT() asm volatile("cp.async.commit_group;" ::: "memory")
#define CP_WAIT0()  asm volatile("cp.async.wait_group 0;" ::: "memory")
#define CP_WAIT1()  asm volatile("cp.async.wait_group 1;" ::: "memory")
#define CP_WAIT2()  asm volatile("cp.async.wait_group 2;" ::: "memory")
#define EX2F(d, s)     asm("ex2.approx.f32 %0, %1;" : "=f"(d) : "f"(s))
#define LDMX4(r, addr) \
    asm volatile("ldmatrix.sync.aligned.m8n8.x4.shared.b16 {%0,%1,%2,%3}, [%4];" \
        : "=r"((r)[0]), "=r"((r)[1]), "=r"((r)[2]), "=r"((r)[3]) : "r"(addr))

__device__ __forceinline__ void mma_f16(float* c, const uint32_t* a, uint32_t b0, uint32_t b1) {
    asm volatile(
        "mma.sync.aligned.m16n8k16.row.col.f32.f16.f16.f32 "
        "{%0,%1,%2,%3}, {%4,%5,%6,%7}, {%8,%9}, {%0,%1,%2,%3};"
        : "+f"(c[0]), "+f"(c[1]), "+f"(c[2]), "+f"(c[3])
        : "r"(a[0]), "r"(a[1]), "r"(a[2]), "r"(a[3]), "r"(b0), "r"(b1));
}

// ================= f16 GEMM: qkv cols single-mma, gate cols split-A; 3-stage pipeline =================
#define GBM 128
#define GBN 128
#define APB 80
#define A_SB (128 * APB)
#define STAGE_B (3 * A_SB)
#define GEMM_SMEM (3 * STAGE_B)     // 92160 B, 2 CTAs/SM

__device__ __forceinline__ void gemm_stage_load(const __half* __restrict__ Ahi,
                                                const __half* __restrict__ Alo,
                                                const __half* __restrict__ Bt,
                                                int K, int m0, int n0, int kt,
                                                uint32_t sbase, int tid, bool lo) {
#pragma unroll
    for (int i = 0; i < 2; i++) {
        int c = tid + i * 256;
        int r = c >> 2, c16 = c & 3;
        uint32_t off = (uint32_t)(r * APB + c16 * 16);
        size_t ga = (size_t)(m0 + r) * K + kt * 32 + c16 * 8;
        size_t gb = (size_t)(n0 + r) * K + kt * 32 + c16 * 8;
        CP_ASYNC16(sbase + off,              Ahi + ga);
        if (lo) CP_ASYNC16(sbase + A_SB + off, Alo + ga);
        CP_ASYNC16(sbase + 2 * A_SB + off,   Bt + gb);
    }
    CP_COMMIT();
}

__global__ void __launch_bounds__(256, 2) gemm_f16_kernel(const __half* __restrict__ Ahi,
                                                          const __half* __restrict__ Alo,
                                                          const __half* __restrict__ Bt,
                                                          float* __restrict__ C,
                                                          int N, int K) {
    extern __shared__ char smraw[];
    uint32_t sm_b = smem_u32(smraw);
    const int tid = threadIdx.x;
    const int wid = tid >> 5;
    const int lane = tid & 31;
    const int warpM = wid & 1;
    const int warpN = wid >> 1;
    const int m0 = blockIdx.y * GBM;
    const int n0 = (gridDim.x - 1 - blockIdx.x) * GBN;   // gate tiles (2x work) scheduled first
    const bool lo = (n0 >= QKV_N);
    const int NT = K / 32;
    const int lr = lane >> 2;
    const int lc = lane & 3;
    const int lm_row = lane & 15;
    const int lm_hi  = (lane >> 4) * 16;

    float acc[4][4][4];
#pragma unroll
    for (int i = 0; i < 4; i++)
#pragma unroll
        for (int j = 0; j < 4; j++)
#pragma unroll
            for (int u = 0; u < 4; u++) acc[i][j][u] = 0.0f;

    // prologue: stages 0, 1 in flight
    gemm_stage_load(Ahi, Alo, Bt, K, m0, n0, 0, sm_b, tid, lo);
    gemm_stage_load(Ahi, Alo, Bt, K, m0, n0, 1, sm_b + STAGE_B, tid, lo);

    int buf = 0;   // buffer of stage kt
    for (int kt = 0; kt < NT; kt++) {
        if (kt + 1 < NT) { CP_WAIT1(); } else { CP_WAIT0(); }   // stage kt resident
        __syncthreads();                                        // also frees buffer (kt+2)%3
        if (kt + 2 < NT) {
            int nbuf = buf + 2; if (nbuf >= 3) nbuf -= 3;
            gemm_stage_load(Ahi, Alo, Bt, K, m0, n0, kt + 2,
                            sm_b + (uint32_t)(nbuf * STAGE_B), tid, lo);
        }

        uint32_t sA = sm_b + (uint32_t)(buf * STAGE_B);
        uint32_t a_base = sA + (uint32_t)((warpM * 64 + lm_row) * APB + lm_hi);
        uint32_t b_base = sA + 2u * A_SB + (uint32_t)((warpN * 32 + lm_row) * APB + lm_hi);

#pragma unroll
        for (int half = 0; half < 2; half++) {
            uint32_t hb = (uint32_t)(half * 32);
            uint32_t bh[2][4];
#pragma unroll
            for (int nb = 0; nb < 2; nb++)
                LDMX4(bh[nb], b_base + (uint32_t)(nb * 16 * APB) + hb);
#pragma unroll
            for (int ma = 0; ma < 4; ma++) {
                uint32_t ah[4], al[4];
                uint32_t addr = a_base + (uint32_t)(ma * 16 * APB) + hb;
                LDMX4(ah, addr);
                if (lo) LDMX4(al, addr + A_SB);
#pragma unroll
                for (int na = 0; na < 4; na++) {
                    int nb = na >> 1, j = na & 1;
                    mma_f16(acc[ma][na], ah, bh[nb][j], bh[nb][j + 2]);
                    if (lo) mma_f16(acc[ma][na], al, bh[nb][j], bh[nb][j + 2]);
                }
            }
        }
        buf++; if (buf == 3) buf = 0;
    }

#pragma unroll
    for (int ma = 0; ma < 4; ma++) {
        int r0 = m0 + warpM * 64 + ma * 16 + lr;
#pragma unroll
        for (int na = 0; na < 4; na++) {
            int c0 = n0 + warpN * 32 + na * 8 + lc * 2;
            *(float2*)(C + (size_t)r0 * N + c0)       = make_float2(acc[ma][na][0], acc[ma][na][1]);
            *(float2*)(C + (size_t)(r0 + 8) * N + c0) = make_float2(acc[ma][na][2], acc[ma][na][3]);
        }
    }
}

// ================= pre-kernels =================
__global__ void splitx_f16_kernel(const float* __restrict__ x,
                                  __half* __restrict__ xhi,
                                  __half* __restrict__ xlo, int n4) {
    int i = blockIdx.x * blockDim.x + threadIdx.x;
    if (i < n4) {
        float4 v = ((const float4*)x)[i];
        float f[4] = {v.x, v.y, v.z, v.w};
        __half h[4], l[4];
#pragma unroll
        for (int j = 0; j < 4; j++) {
            h[j] = __float2half_rn(f[j]);
            l[j] = __float2half_rn(f[j] - __half2float(h[j]));
        }
        ((uint2*)xhi)[i] = *(uint2*)h;
        ((uint2*)xlo)[i] = *(uint2*)l;
    }
}

__global__ void wt_f16_kernel(const float* __restrict__ W,
                              __half* __restrict__ WT,
                              int K, int Nc, int nrow_off) {
    __shared__ float tile[32][33];
    int n0 = blockIdx.x * 32, k0 = blockIdx.y * 32;
    int tx = threadIdx.x, ty = threadIdx.y;
#pragma unroll
    for (int i = 0; i < 4; i++)
        tile[ty + i * 8][tx] = W[(size_t)(k0 + ty + i * 8) * Nc + n0 + tx];
    __syncthreads();
#pragma unroll
    for (int i = 0; i < 4; i++) {
        float v = tile[tx][ty + i * 8];
        WT[(size_t)(nrow_off + n0 + ty + i * 8) * K + k0 + tx] = __float2half_rn(v);
    }
}

// ---------------- prep: rmsnorm(q,k) + RoPE -> f16 ----------------
__global__ void prep_kernel() {
    int t = blockIdx.x, h = blockIdx.y, b = blockIdx.z;
    int d = threadIdx.x;
    const float* p = g_C + ((size_t)(b * T_ + t)) * CN + h * 384;
    float qv = p[d], kv = p[128 + d], vv = p[256 + d];

    __shared__ float redq[4], redk[4];
    __shared__ float qs[128], ks[128];
    float q2 = qv * qv, k2 = kv * kv;
#pragma unroll
    for (int off = 16; off > 0; off >>= 1) {
        q2 += __shfl_xor_sync(0xffffffffu, q2, off);
        k2 += __shfl_xor_sync(0xffffffffu, k2, off);
    }
    if ((d & 31) == 0) { redq[d >> 5] = q2; redk[d >> 5] = k2; }
    __syncthreads();
    float sq = redq[0] + redq[1] + redq[2] + redq[3];
    float sk = redk[0] + redk[1] + redk[2] + redk[3];
    float qn = qv * rsqrtf(sq * (1.0f / 128.0f) + 1e-6f);
    float kn = kv * rsqrtf(sk * (1.0f / 128.0f) + 1e-6f);
    qs[d] = qn; ks[d] = kn;
    __syncthreads();

    int dd = d & 63;
    float freq = (float)t * expf(-(float)dd * (9.210340371976184f / 64.0f));
    float c = cosf(freq), s = sinf(freq);
    float qr, kr;
    if (d < 64) { qr =  qs[d] * c + qs[d + 64] * s;  kr =  ks[d] * c + ks[d + 64] * s; }
    else        { qr = -qs[dd] * s + qs[d] * c;      kr = -ks[dd] * s + ks[d] * c;     }

    const float QSCL = 0.08838834764831845f * 1.44269504088896340f;
    size_t qi = ((size_t)(b * NH + h) * T_ + t) * HD + d;
    g_Qh[qi] = __float2half_rn(qr * QSCL);
    g_Kh[qi] = __float2half_rn(kr);
    size_t vi = ((size_t)(b * HP_ + (h >> 1)) * T_ + t) * 256 + (size_t)(h & 1) * 128 + d;
    g_Vh[vi] = __float2half_rn(vv);
}

// ---------------- V transpose (f16) ----------------
__global__ void vtrans_kernel() {
    __shared__ __half tile[32][34];
    int t0 = blockIdx.x * 32, e0 = blockIdx.y * 32, bhp = blockIdx.z;
    const __half* src = g_Vh + (size_t)bhp * T_ * 256;
    __half* dst = g_Vth + (size_t)bhp * 256 * T_;
    int tx = threadIdx.x, ty = threadIdx.y;
#pragma unroll
    for (int i = 0; i < 4; i++)
        tile[ty + i * 8][tx] = src[(size_t)(t0 + ty + i * 8) * 256 + e0 + tx];
    __syncthreads();
#pragma unroll
    for (int i = 0; i < 4; i++)
        dst[(size_t)(e0 + ty + i * 8) * T_ + t0 + tx] = tile[tx][ty + i * 8];
}

// ---------------- lambda ----------------
__global__ void lam_kernel(const float* __restrict__ lq1, const float* __restrict__ lk1,
                           const float* __restrict__ lq2, const float* __restrict__ lk2) {
    int hp = threadIdx.y;
    int lane = threadIdx.x;
    float s1 = lq1[hp*64 + lane] * lk1[hp*64 + lane] + lq1[hp*64 + lane + 32] * lk1[hp*64 + lane + 32];
    float s2 = lq2[hp*64 + lane] * lk2[hp*64 + lane] + lq2[hp*64 + lane + 32] * lk2[hp*64 + lane + 32];
#pragma unroll
    for (int off = 16; off > 0; off >>= 1) {
        s1 += __shfl_xor_sync(0xffffffffu, s1, off);
        s2 += __shfl_xor_sync(0xffffffffu, s2, off);
    }
    if (lane == 0) g_lam[hp] = expf(s1) - expf(s2) + LAMBDA_INIT;
}

// ---------------- flash attention, f16 mma ----------------
#define QS_B   0
#define KS0_B  17408
#define KS1_B  34816
#define VT_B   52224
#define PS_B   89088
#define WMAX_B 98304
#define WSUM_B 98816
#define ATT_SMEM 99328

__global__ void __launch_bounds__(256, 2) attn_kernel() {
    const int mt = gridDim.x - 1 - blockIdx.x;
    const int h = blockIdx.y, b = blockIdx.z;
    const int tid = threadIdx.x, wid = tid >> 5, lane = tid & 31;
    const int wM = wid & 3, wN = wid >> 2;
    const int lr = lane >> 2, lc = lane & 3;
    const int r0 = wM * 16 + lr;
    const int lm_row = lane & 15;
    const int lm_hi  = (lane >> 4) * 16;

    extern __shared__ char smc[];
    uint32_t smb = smem_u32(smc);
    float* wmaxs = (float*)(smc + WMAX_B);
    float* wsums = (float*)(smc + WSUM_B);

    const __half* Qg  = g_Qh  + ((size_t)(b * NH + h) * T_ + (size_t)mt * 64) * HD;
    const __half* Kg  = g_Kh  + (size_t)(b * NH + h) * T_ * HD;
    const __half* Vtg = g_Vth + (size_t)(b * HP_ + (h >> 1)) * 256 * T_;
    float*        Yg  = g_Y   + (size_t)(b * NH + h) * T_ * 256;

#pragma unroll
    for (int i = 0; i < 4; i++) {
        int idx = tid + i * 256;
        int r = idx >> 4, c16 = idx & 15;
        CP_ASYNC16(smb + (uint32_t)(KS0_B + r * 272 + c16 * 16),
                   Kg + (size_t)r * HD + c16 * 8);
    }
    CP_COMMIT();
#pragma unroll
    for (int i = 0; i < 4; i++) {
        int idx = tid + i * 256;
        int r = idx >> 4, c16 = idx & 15;
        CP_ASYNC16(smb + (uint32_t)(QS_B + r * 272 + c16 * 16),
                   Qg + (size_t)r * HD + c16 * 8);
    }
    CP_COMMIT();

    float O[16][4];
#pragma unroll
    for (int i = 0; i < 16; i++)
#pragma unroll
        for (int j = 0; j < 4; j++) O[i][j] = 0.0f;
    float m0 = -1e30f, m1 = -1e30f, l0 = 0.0f, l1 = 0.0f;

    const uint32_t qs_base  = smb + (uint32_t)(QS_B  + (wM * 16 + lm_row) * 272 + lm_hi);
    const uint32_t ks_base0 = smb + (uint32_t)(KS0_B + (wN * 32 + lm_row) * 272 + lm_hi);
    const uint32_t ks_base1 = smb + (uint32_t)(KS1_B + (wN * 32 + lm_row) * 272 + lm_hi);
    const uint32_t ps_base  = smb + (uint32_t)(PS_B  + (wM * 16 + lm_row) * 144 + lm_hi);
    const uint32_t vt_base  = smb + (uint32_t)(VT_B  + (wN * 128 + lm_row) * 144 + lm_hi);

    for (int nt = 0; nt <= mt; nt++) {
        __syncthreads();
#pragma unroll
        for (int i = 0; i < 8; i++) {
            int idx = tid + i * 256;
            int r = idx >> 3, c = idx & 7;
            CP_ASYNC16(smb + (uint32_t)(VT_B + r * 144 + c * 16),
                       Vtg + (size_t)r * T_ + nt * 64 + c * 8);
        }
        CP_COMMIT();
        if (nt < mt) {
            int koff = ((nt + 1) & 1) ? KS1_B : KS0_B;
#pragma unroll
            for (int i = 0; i < 4; i++) {
                int idx = tid + i * 256;
                int r = idx >> 4, c16 = idx & 15;
                CP_ASYNC16(smb + (uint32_t)(koff + r * 272 + c16 * 16),
                           Kg + (size_t)((nt + 1) * 64 + r) * HD + c16 * 8);
            }
            CP_COMMIT();
        }
        if (nt < mt) { CP_WAIT2(); } else { CP_WAIT1(); }
        __syncthreads();

        uint32_t kb_base = (nt & 1) ? ks_base1 : ks_base0;
        float accS[4][4];
#pragma unroll
        for (int na = 0; na < 4; na++)
#pragma unroll
            for (int u = 0; u < 4; u++) accS[na][u] = 0.0f;
#pragma unroll 4
        for (int ks = 0; ks < 8; ks++) {
            uint32_t ah[4];
            LDMX4(ah, qs_base + ks * 32u);
#pragma unroll
            for (int pr = 0; pr < 2; pr++) {
                uint32_t kb[4];
                LDMX4(kb, kb_base + (uint32_t)(pr * 16 * 272) + ks * 32u);
                mma_f16(accS[pr * 2],     ah, kb[0], kb[2]);
                mma_f16(accS[pr * 2 + 1], ah, kb[1], kb[3]);
            }
        }

        if (nt == mt) {
#pragma unroll
            for (int na = 0; na < 4; na++) {
                int col = wN * 32 + na * 8 + 2 * lc;
                if (col     > r0)     accS[na][0] = -1e30f;
                if (col + 1 > r0)     accS[na][1] = -1e30f;
                if (col     > r0 + 8) accS[na][2] = -1e30f;
                if (col + 1 > r0 + 8) accS[na][3] = -1e30f;
            }
        }

        float mx0 = -1e30f, mx1 = -1e30f;
#pragma unroll
        for (int na = 0; na < 4; na++) {
            mx0 = fmaxf(mx0, fmaxf(accS[na][0], accS[na][1]));
            mx1 = fmaxf(mx1, fmaxf(accS[na][2], accS[na][3]));
        }
        mx0 = fmaxf(mx0, __shfl_xor_sync(0xffffffffu, mx0, 1));
        mx0 = fmaxf(mx0, __shfl_xor_sync(0xffffffffu, mx0, 2));
        mx1 = fmaxf(mx1, __shfl_xor_sync(0xffffffffu, mx1, 1));
        mx1 = fmaxf(mx1, __shfl_xor_sync(0xffffffffu, mx1, 2));
        if ((lane & 3) == 0) {
            wmaxs[wN * 64 + r0]     = mx0;
            wmaxs[wN * 64 + r0 + 8] = mx1;
        }
        __syncthreads();
        float mn0 = fmaxf(m0, fmaxf(wmaxs[r0], wmaxs[64 + r0]));
        float mn1 = fmaxf(m1, fmaxf(wmaxs[r0 + 8], wmaxs[64 + r0 + 8]));
        float a0, a1;
        EX2F(a0, m0 - mn0);
        EX2F(a1, m1 - mn1);
        float s0 = 0.0f, s1 = 0.0f;
#pragma unroll
        for (int na = 0; na < 4; na++) {
            float p00, p01, p10, p11;
            EX2F(p00, accS[na][0] - mn0);
            EX2F(p01, accS[na][1] - mn0);
            EX2F(p10, accS[na][2] - mn1);
            EX2F(p11, accS[na][3] - mn1);
            __half hp00 = __float2half_rn(p00), hp01 = __float2half_rn(p01);
            __half hp10 = __float2half_rn(p10), hp11 = __float2half_rn(p11);
            s0 += __half2float(hp00) + __half2float(hp01);
            s1 += __half2float(hp10) + __half2float(hp11);
            int col = wN * 32 + na * 8 + 2 * lc;
            *(__half2*)(smc + PS_B + r0 * 144 + col * 2)       = __halves2half2(hp00, hp01);
            *(__half2*)(smc + PS_B + (r0 + 8) * 144 + col * 2) = __halves2half2(hp10, hp11);
        }
        s0 += __shfl_xor_sync(0xffffffffu, s0, 1);
        s0 += __shfl_xor_sync(0xffffffffu, s0, 2);
        s1 += __shfl_xor_sync(0xffffffffu, s1, 1);
        s1 += __shfl_xor_sync(0xffffffffu, s1, 2);
        if ((lane & 3) == 0) {
            wsums[wN * 64 + r0]     = s0;
            wsums[wN * 64 + r0 + 8] = s1;
        }
        if (nt < mt) { CP_WAIT1(); } else { CP_WAIT0(); }
        __syncthreads();
        l0 = l0 * a0 + wsums[r0] + wsums[64 + r0];
        l1 = l1 * a1 + wsums[r0 + 8] + wsums[64 + r0 + 8];
        m0 = mn0; m1 = mn1;
#pragma unroll
        for (int i = 0; i < 16; i++) {
            O[i][0] *= a0; O[i][1] *= a0; O[i][2] *= a1; O[i][3] *= a1;
        }

#pragma unroll 2
        for (int ks = 0; ks < 4; ks++) {
            uint32_t pf[4];
            LDMX4(pf, ps_base + ks * 32u);
#pragma unroll
            for (int pr = 0; pr < 8; pr++) {
                uint32_t vb[4];
                LDMX4(vb, vt_base + (uint32_t)(pr * 16 * 144) + ks * 32u);
                mma_f16(O[pr * 2],     pf, vb[0], vb[2]);
                mma_f16(O[pr * 2 + 1], pf, vb[1], vb[3]);
            }
        }
    }

    float i0, i1;
    asm("rcp.approx.f32 %0, %1;" : "=f"(i0) : "f"(l0));
    asm("rcp.approx.f32 %0, %1;" : "=f"(i1) : "f"(l1));
    int tg0 = mt * 64 + r0;
#pragma unroll
    for (int na = 0; na < 16; na++) {
        int col = wN * 128 + na * 8 + 2 * lc;
        *(float2*)(Yg + (size_t)tg0 * 256 + col)       = make_float2(O[na][0] * i0, O[na][1] * i0);
        *(float2*)(Yg + (size_t)(tg0 + 8) * 256 + col) = make_float2(O[na][2] * i1, O[na][3] * i1);
    }
}

// ---------------- combine ----------------
__global__ void combine_kernel(float* __restrict__ out) {
    int t = blockIdx.x, hp = blockIdx.y, b = blockIdx.z;
    int e = threadIdx.x;
    size_t y1i = ((size_t)(b * NH + 2 * hp)     * T_ + t) * 256 + e;
    size_t y2i = ((size_t)(b * NH + 2 * hp + 1) * T_ + t) * 256 + e;
    float y1 = g_Y[y1i], y2 = g_Y[y2i];
    float lam = g_lam[hp];
    float gv = g_C[((size_t)(b * T_ + t)) * CN + QKV_N + hp * 256 + e];
    float sg = gv / (1.0f + expf(-gv));
    float yv = (y1 - lam * y2) * sg;

    __shared__ float red[8];
    float s = yv * yv;
#pragma unroll
    for (int off = 16; off > 0; off >>= 1)
        s += __shfl_xor_sync(0xffffffffu, s, off);
    if ((e & 31) == 0) red[e >> 5] = s;
    __syncthreads();
    float tot = 0.0f;
#pragma unroll
    for (int w = 0; w < 8; w++) tot += red[w];
    float r = rsqrtf(tot * (1.0f / 256.0f) + 1e-6f) * ONE_MINUS_LI;
    out[((size_t)(b * T_ + t)) * DM + hp * 256 + e] = yv * r;
}

// ---------------- launch ----------------
extern "C" void kernel_launch(void* const* d_in, const int* in_sizes, int n_in,
                              void* d_out, int out_size) {
    const float* x    = (const float*)d_in[0];
    const float* Wqkv = (const float*)d_in[1];
    const float* lq1  = (const float*)d_in[2];
    const float* lk1  = (const float*)d_in[3];
    const float* lq2  = (const float*)d_in[4];
    const float* lk2  = (const float*)d_in[5];
    const float* Wg   = (const float*)d_in[6];
    float* out = (float*)d_out;

    float *c_p;
    __half *xhi_p, *xlo_p, *wt_p;
    cudaGetSymbolAddress((void**)&c_p,   g_C);
    cudaGetSymbolAddress((void**)&xhi_p, g_Xhi);
    cudaGetSymbolAddress((void**)&xlo_p, g_Xlo);
    cudaGetSymbolAddress((void**)&wt_p,  g_WT);

    int nx4 = B_ * T_ * DM / 4;
    splitx_f16_kernel<<<(nx4 + 255) / 256, 256>>>(x, xhi_p, xlo_p, nx4);
    wt_f16_kernel<<<dim3(QKV_N / 32, DM / 32), dim3(32, 8)>>>(Wqkv, wt_p, DM, QKV_N, 0);
    wt_f16_kernel<<<dim3(DM / 32,    DM / 32), dim3(32, 8)>>>(Wg,   wt_p, DM, DM, QKV_N);

    cudaFuncSetAttribute(gemm_f16_kernel, cudaFuncAttributeMaxDynamicSharedMemorySize, GEMM_SMEM);
    gemm_f16_kernel<<<dim3(CN / GBN, (B_ * T_) / GBM), 256, GEMM_SMEM>>>(xhi_p, xlo_p, wt_p, c_p, CN, DM);

    prep_kernel<<<dim3(T_, NH, B_), 128>>>();
    vtrans_kernel<<<dim3(T_ / 32, 256 / 32, B_ * HP_), dim3(32, 8)>>>();
    lam_kernel<<<1, dim3(32, 8)>>>(lq1, lk1, lq2, lk2);
    cudaFuncSetAttribute(attn_kernel, cudaFuncAttributeMaxDynamicSharedMemorySize, ATT_SMEM);
    attn_kernel<<<dim3(T_ / 64, NH, B_), 256, ATT_SMEM>>>();
    combine_kernel<<<dim3(T_, HP_, B_), 256>>>(out);
}

// round 12
// speedup vs baseline: 2.0479x; 1.0215x over previous
#include <cuda_runtime.h>
#include <cuda_fp16.h>
#include <math.h>
#include <cstdint>

#define B_   2
#define T_   2048
#define DM   2048
#define NH   16
#define HD   128
#define HP_  8
#define QKV_N 6144
#define CN   8192
#define LAMBDA_INIT  0.7008206670670481f
#define ONE_MINUS_LI 0.2991793329329519f
#define QSCL (0.08838834764831845f * 1.44269504088896340f)

// ---------------- scratch ----------------
__device__ float g_C[(size_t)B_ * T_ * CN];        // gate region used only
__device__ __half g_Qh[(size_t)B_ * NH * T_ * HD];
__device__ __half g_Kh[(size_t)B_ * NH * T_ * HD];
__device__ __half g_Vth[(size_t)B_ * HP_ * 256 * T_];
__device__ float g_Y[(size_t)B_ * NH * T_ * 256];
__device__ float g_lam[HP_];
__device__ __half g_Xhi[(size_t)B_ * T_ * DM];
__device__ __half g_Xlo[(size_t)B_ * T_ * DM];
__device__ __half g_WT[(size_t)CN * DM];
__device__ float g_cos[(size_t)T_ * 64];
__device__ float g_sin[(size_t)T_ * 64];

// ================= helpers =================
__device__ __forceinline__ uint32_t smem_u32(const void* p) {
    uint32_t a;
    asm("{ .reg .u64 t; cvta.to.shared.u64 t, %1; cvt.u32.u64 %0, t; }" : "=r"(a) : "l"(p));
    return a;
}
#define CP_ASYNC16(dst, src) \
    asm volatile("cp.async.cg.shared.global [%0], [%1], 16;" :: "r"(dst), "l"(src) : "memory")
#define CP_COMMIT() asm volatile("cp.async.commit_group;" ::: "memory")
#define CP_WAIT0()  asm volatile("cp.async.wait_group 0;" ::: "memory")
#define CP_WAIT1()  asm volatile("cp.async.wait_group 1;" ::: "memory")
#define CP_WAIT2()  asm volatile("cp.async.wait_group 2;" ::: "memory")
#define EX2F(d, s)     asm("ex2.approx.f32 %0, %1;" : "=f"(d) : "f"(s))
#define LDMX4(r, addr) \
    asm volatile("ldmatrix.sync.aligned.m8n8.x4.shared.b16 {%0,%1,%2,%3}, [%4];" \
        : "=r"((r)[0]), "=r"((r)[1]), "=r"((r)[2]), "=r"((r)[3]) : "r"(addr))

__device__ __forceinline__ void mma_f16(float* c, const uint32_t* a, uint32_t b0, uint32_t b1) {
    asm volatile(
        "mma.sync.aligned.m16n8k16.row.col.f32.f16.f16.f32 "
        "{%0,%1,%2,%3}, {%4,%5,%6,%7}, {%8,%9}, {%0,%1,%2,%3};"
        : "+f"(c[0]), "+f"(c[1]), "+f"(c[2]), "+f"(c[3])
        : "r"(a[0]), "r"(a[1]), "r"(a[2]), "r"(a[3]), "r"(b0), "r"(b1));
}

// ================= f16 GEMM + fused qkv epilogue =================
#define GBM 128
#define GBN 128
#define APB 80
#define A_SB (128 * APB)
#define STAGE_B (3 * A_SB)
#define GEMM_SMEM (3 * STAGE_B)     // 92160 B; staging area 128*132*4=67584 fits

__device__ __forceinline__ void gemm_stage_load(const __half* __restrict__ Ahi,
                                                const __half* __restrict__ Alo,
                                                const __half* __restrict__ Bt,
                                                int K, int m0, int n0, int kt,
                                                uint32_t sbase, int tid, bool lo) {
#pragma unroll
    for (int i = 0; i < 2; i++) {
        int c = tid + i * 256;
        int r = c >> 2, c16 = c & 3;
        uint32_t off = (uint32_t)(r * APB + c16 * 16);
        size_t ga = (size_t)(m0 + r) * K + kt * 32 + c16 * 8;
        size_t gb = (size_t)(n0 + r) * K + kt * 32 + c16 * 8;
        CP_ASYNC16(sbase + off,              Ahi + ga);
        if (lo) CP_ASYNC16(sbase + A_SB + off, Alo + ga);
        CP_ASYNC16(sbase + 2 * A_SB + off,   Bt + gb);
    }
    CP_COMMIT();
}

__global__ void __launch_bounds__(256, 2) gemm_f16_kernel(const __half* __restrict__ Ahi,
                                                          const __half* __restrict__ Alo,
                                                          const __half* __restrict__ Bt,
                                                          float* __restrict__ C,
                                                          int N, int K) {
    extern __shared__ char smraw[];
    uint32_t sm_b = smem_u32(smraw);
    float* sf = (float*)smraw;          // epilogue staging (128 x pitch132)
    const int tid = threadIdx.x;
    const int wid = tid >> 5;
    const int lane = tid & 31;
    const int warpM = wid & 1;
    const int warpN = wid >> 1;
    const int m0 = blockIdx.y * GBM;
    const int n0 = (gridDim.x - 1 - blockIdx.x) * GBN;   // gate tiles (2x work) first
    const bool lo = (n0 >= QKV_N);
    const int NT = K / 32;
    const int lr = lane >> 2;
    const int lc = lane & 3;
    const int lm_row = lane & 15;
    const int lm_hi  = (lane >> 4) * 16;

    float acc[4][4][4];
#pragma unroll
    for (int i = 0; i < 4; i++)
#pragma unroll
        for (int j = 0; j < 4; j++)
#pragma unroll
            for (int u = 0; u < 4; u++) acc[i][j][u] = 0.0f;

    gemm_stage_load(Ahi, Alo, Bt, K, m0, n0, 0, sm_b, tid, lo);
    gemm_stage_load(Ahi, Alo, Bt, K, m0, n0, 1, sm_b + STAGE_B, tid, lo);

    int buf = 0;
    for (int kt = 0; kt < NT; kt++) {
        if (kt + 1 < NT) { CP_WAIT1(); } else { CP_WAIT0(); }
        __syncthreads();
        if (kt + 2 < NT) {
            int nbuf = buf + 2; if (nbuf >= 3) nbuf -= 3;
            gemm_stage_load(Ahi, Alo, Bt, K, m0, n0, kt + 2,
                            sm_b + (uint32_t)(nbuf * STAGE_B), tid, lo);
        }

        uint32_t sA = sm_b + (uint32_t)(buf * STAGE_B);
        uint32_t a_base = sA + (uint32_t)((warpM * 64 + lm_row) * APB + lm_hi);
        uint32_t b_base = sA + 2u * A_SB + (uint32_t)((warpN * 32 + lm_row) * APB + lm_hi);

#pragma unroll
        for (int half = 0; half < 2; half++) {
            uint32_t hb = (uint32_t)(half * 32);
            uint32_t bh[2][4];
#pragma unroll
            for (int nb = 0; nb < 2; nb++)
                LDMX4(bh[nb], b_base + (uint32_t)(nb * 16 * APB) + hb);
#pragma unroll
            for (int ma = 0; ma < 4; ma++) {
                uint32_t ah[4], al[4];
                uint32_t addr = a_base + (uint32_t)(ma * 16 * APB) + hb;
                LDMX4(ah, addr);
                if (lo) LDMX4(al, addr + A_SB);
#pragma unroll
                for (int na = 0; na < 4; na++) {
                    int nb = na >> 1, j = na & 1;
                    mma_f16(acc[ma][na], ah, bh[nb][j], bh[nb][j + 2]);
                    if (lo) mma_f16(acc[ma][na], al, bh[nb][j], bh[nb][j + 2]);
                }
            }
        }
        buf++; if (buf == 3) buf = 0;
    }

    if (lo) {
        // gate tiles: plain fp32 store to g_C
#pragma unroll
        for (int ma = 0; ma < 4; ma++) {
            int r0 = m0 + warpM * 64 + ma * 16 + lr;
#pragma unroll
            for (int na = 0; na < 4; na++) {
                int c0 = n0 + warpN * 32 + na * 8 + lc * 2;
                *(float2*)(C + (size_t)r0 * N + c0)       = make_float2(acc[ma][na][0], acc[ma][na][1]);
                *(float2*)(C + (size_t)(r0 + 8) * N + c0) = make_float2(acc[ma][na][2], acc[ma][na][3]);
            }
        }
        return;
    }

    // ---- fused qkv epilogue ----
    __syncthreads();   // all warps done reading stage buffers
#pragma unroll
    for (int ma = 0; ma < 4; ma++) {
        int r = warpM * 64 + ma * 16 + lr;
#pragma unroll
        for (int na = 0; na < 4; na++) {
            int c = warpN * 32 + na * 8 + lc * 2;
            *(float2*)(sf + r * 132 + c)       = make_float2(acc[ma][na][0], acc[ma][na][1]);
            *(float2*)(sf + (r + 8) * 132 + c) = make_float2(acc[ma][na][2], acc[ma][na][3]);
        }
    }
    __syncthreads();

    const int tile3 = (n0 >> 7) % 3;     // 0=q, 1=k, 2=v
    const int h = n0 / 384;
    const int bb = m0 / T_;
    const int t0 = m0 % T_;

    if (tile3 == 2) {
        // v: transposed f16 write to g_Vth[(b*HP+hp)*256 + e][t]
        int c = tid >> 1, rh = (tid & 1) * 64;
        int e = ((h & 1) << 7) + c;
        __half* dst = g_Vth + ((size_t)(bb * HP_ + (h >> 1)) * 256 + e) * T_ + t0 + rh;
#pragma unroll
        for (int r8 = 0; r8 < 64; r8 += 8) {
            __half2 p[4];
#pragma unroll
            for (int j = 0; j < 4; j++) {
                float a  = sf[(rh + r8 + 2 * j)     * 132 + c];
                float b2 = sf[(rh + r8 + 2 * j + 1) * 132 + c];
                p[j] = __halves2half2(__float2half_rn(a), __float2half_rn(b2));
            }
            *(uint4*)(dst + r8) = *(uint4*)p;
        }
    } else {
        // q/k: rmsnorm + rope -> f16
        int r = tid >> 1, half = tid & 1;
        const float* row = sf + r * 132;
        float ss = 0.0f;
#pragma unroll 8
        for (int i = 0; i < 64; i++) {
            float v = row[half * 64 + i];
            ss += v * v;
        }
        ss += __shfl_xor_sync(0xffffffffu, ss, 1);
        float rq = rsqrtf(ss * (1.0f / 128.0f) + 1e-6f);
        if (tile3 == 0) rq *= QSCL;
        int t = t0 + r;
        const float* ctab = g_cos + (size_t)t * 64;
        const float* stab = g_sin + (size_t)t * 64;
        __half* dst = ((tile3 == 0) ? g_Qh : g_Kh)
                      + ((size_t)(bb * NH + h) * T_ + t) * HD + half * 64;
#pragma unroll
        for (int i8 = 0; i8 < 64; i8 += 8) {
            __half2 p[4];
#pragma unroll
            for (int j = 0; j < 4; j++) {
                float o2[2];
#pragma unroll
                for (int u = 0; u < 2; u++) {
                    int i = i8 + 2 * j + u;
                    float cs = ctab[i], sn = stab[i];
                    float xa = row[i] * rq, xb = row[i + 64] * rq;
                    o2[u] = half ? (-xa * sn + xb * cs) : (xa * cs + xb * sn);
                }
                p[j] = __halves2half2(__float2half_rn(o2[0]), __float2half_rn(o2[1]));
            }
            *(uint4*)(dst + i8) = *(uint4*)p;
        }
    }
}

// ================= pre-kernels =================
__global__ void rope_tab_kernel() {
    int t = blockIdx.x, i = threadIdx.x;   // 64 threads
    float invf = expf(-(float)i * (9.210340371976184f / 64.0f));
    float fr = (float)t * invf;
    g_cos[(size_t)t * 64 + i] = cosf(fr);
    g_sin[(size_t)t * 64 + i] = sinf(fr);
}

__global__ void splitx_f16_kernel(const float* __restrict__ x,
                                  __half* __restrict__ xhi,
                                  __half* __restrict__ xlo, int n4) {
    int i = blockIdx.x * blockDim.x + threadIdx.x;
    if (i < n4) {
        float4 v = ((const float4*)x)[i];
        float f[4] = {v.x, v.y, v.z, v.w};
        __half h[4], l[4];
#pragma unroll
        for (int j = 0; j < 4; j++) {
            h[j] = __float2half_rn(f[j]);
            l[j] = __float2half_rn(f[j] - __half2float(h[j]));
        }
        ((uint2*)xhi)[i] = *(uint2*)h;
        ((uint2*)xlo)[i] = *(uint2*)l;
    }
}

__global__ void wt_f16_kernel(const float* __restrict__ W,
                              __half* __restrict__ WT,
                              int K, int Nc, int nrow_off) {
    __shared__ float tile[32][33];
    int n0 = blockIdx.x * 32, k0 = blockIdx.y * 32;
    int tx = threadIdx.x, ty = threadIdx.y;
#pragma unroll
    for (int i = 0; i < 4; i++)
        tile[ty + i * 8][tx] = W[(size_t)(k0 + ty + i * 8) * Nc + n0 + tx];
    __syncthreads();
#pragma unroll
    for (int i = 0; i < 4; i++) {
        float v = tile[tx][ty + i * 8];
        WT[(size_t)(nrow_off + n0 + ty + i * 8) * K + k0 + tx] = __float2half_rn(v);
    }
}

// ---------------- lambda ----------------
__global__ void lam_kernel(const float* __restrict__ lq1, const float* __restrict__ lk1,
                           const float* __restrict__ lq2, const float* __restrict__ lk2) {
    int hp = threadIdx.y;
    int lane = threadIdx.x;
    float s1 = lq1[hp*64 + lane] * lk1[hp*64 + lane] + lq1[hp*64 + lane + 32] * lk1[hp*64 + lane + 32];
    float s2 = lq2[hp*64 + lane] * lk2[hp*64 + lane] + lq2[hp*64 + lane + 32] * lk2[hp*64 + lane + 32];
#pragma unroll
    for (int off = 16; off > 0; off >>= 1) {
        s1 += __shfl_xor_sync(0xffffffffu, s1, off);
        s2 += __shfl_xor_sync(0xffffffffu, s2, off);
    }
    if (lane == 0) g_lam[hp] = expf(s1) - expf(s2) + LAMBDA_INIT;
}

// ---------------- flash attention, f16 mma (unchanged from R11) ----------------
#define QS_B   0
#define KS0_B  17408
#define KS1_B  34816
#define VT_B   52224
#define PS_B   89088
#define WMAX_B 98304
#define WSUM_B 98816
#define ATT_SMEM 99328

__global__ void __launch_bounds__(256, 2) attn_kernel() {
    const int mt = gridDim.x - 1 - blockIdx.x;
    const int h = blockIdx.y, b = blockIdx.z;
    const int tid = threadIdx.x, wid = tid >> 5, lane = tid & 31;
    const int wM = wid & 3, wN = wid >> 2;
    const int lr = lane >> 2, lc = lane & 3;
    const int r0 = wM * 16 + lr;
    const int lm_row = lane & 15;
    const int lm_hi  = (lane >> 4) * 16;

    extern __shared__ char smc[];
    uint32_t smb = smem_u32(smc);
    float* wmaxs = (float*)(smc + WMAX_B);
    float* wsums = (float*)(smc + WSUM_B);

    const __half* Qg  = g_Qh  + ((size_t)(b * NH + h) * T_ + (size_t)mt * 64) * HD;
    const __half* Kg  = g_Kh  + (size_t)(b * NH + h) * T_ * HD;
    const __half* Vtg = g_Vth + (size_t)(b * HP_ + (h >> 1)) * 256 * T_;
    float*        Yg  = g_Y   + (size_t)(b * NH + h) * T_ * 256;

#pragma unroll
    for (int i = 0; i < 4; i++) {
        int idx = tid + i * 256;
        int r = idx >> 4, c16 = idx & 15;
        CP_ASYNC16(smb + (uint32_t)(KS0_B + r * 272 + c16 * 16),
                   Kg + (size_t)r * HD + c16 * 8);
    }
    CP_COMMIT();
#pragma unroll
    for (int i = 0; i < 4; i++) {
        int idx = tid + i * 256;
        int r = idx >> 4, c16 = idx & 15;
        CP_ASYNC16(smb + (uint32_t)(QS_B + r * 272 + c16 * 16),
                   Qg + (size_t)r * HD + c16 * 8);
    }
    CP_COMMIT();

    float O[16][4];
#pragma unroll
    for (int i = 0; i < 16; i++)
#pragma unroll
        for (int j = 0; j < 4; j++) O[i][j] = 0.0f;
    float m0 = -1e30f, m1 = -1e30f, l0 = 0.0f, l1 = 0.0f;

    const uint32_t qs_base  = smb + (uint32_t)(QS_B  + (wM * 16 + lm_row) * 272 + lm_hi);
    const uint32_t ks_base0 = smb + (uint32_t)(KS0_B + (wN * 32 + lm_row) * 272 + lm_hi);
    const uint32_t ks_base1 = smb + (uint32_t)(KS1_B + (wN * 32 + lm_row) * 272 + lm_hi);
    const uint32_t ps_base  = smb + (uint32_t)(PS_B  + (wM * 16 + lm_row) * 144 + lm_hi);
    const uint32_t vt_base  = smb + (uint32_t)(VT_B  + (wN * 128 + lm_row) * 144 + lm_hi);

    for (int nt = 0; nt <= mt; nt++) {
        __syncthreads();
#pragma unroll
        for (int i = 0; i < 8; i++) {
            int idx = tid + i * 256;
            int r = idx >> 3, c = idx & 7;
            CP_ASYNC16(smb + (uint32_t)(VT_B + r * 144 + c * 16),
                       Vtg + (size_t)r * T_ + nt * 64 + c * 8);
        }
        CP_COMMIT();
        if (nt < mt) {
            int koff = ((nt + 1) & 1) ? KS1_B : KS0_B;
#pragma unroll
            for (int i = 0; i < 4; i++) {
                int idx = tid + i * 256;
                int r = idx >> 4, c16 = idx & 15;
                CP_ASYNC16(smb + (uint32_t)(koff + r * 272 + c16 * 16),
                           Kg + (size_t)((nt + 1) * 64 + r) * HD + c16 * 8);
            }
            CP_COMMIT();
        }
        if (nt < mt) { CP_WAIT2(); } else { CP_WAIT1(); }
        __syncthreads();

        uint32_t kb_base = (nt & 1) ? ks_base1 : ks_base0;
        float accS[4][4];
#pragma unroll
        for (int na = 0; na < 4; na++)
#pragma unroll
            for (int u = 0; u < 4; u++) accS[na][u] = 0.0f;
#pragma unroll 4
        for (int ks = 0; ks < 8; ks++) {
            uint32_t ah[4];
            LDMX4(ah, qs_base + ks * 32u);
#pragma unroll
            for (int pr = 0; pr < 2; pr++) {
                uint32_t kb[4];
                LDMX4(kb, kb_base + (uint32_t)(pr * 16 * 272) + ks * 32u);
                mma_f16(accS[pr * 2],     ah, kb[0], kb[2]);
                mma_f16(accS[pr * 2 + 1], ah, kb[1], kb[3]);
            }
        }

        if (nt == mt) {
#pragma unroll
            for (int na = 0; na < 4; na++) {
                int col = wN * 32 + na * 8 + 2 * lc;
                if (col     > r0)     accS[na][0] = -1e30f;
                if (col + 1 > r0)     accS[na][1] = -1e30f;
                if (col     > r0 + 8) accS[na][2] = -1e30f;
                if (col + 1 > r0 + 8) accS[na][3] = -1e30f;
            }
        }

        float mx0 = -1e30f, mx1 = -1e30f;
#pragma unroll
        for (int na = 0; na < 4; na++) {
            mx0 = fmaxf(mx0, fmaxf(accS[na][0], accS[na][1]));
            mx1 = fmaxf(mx1, fmaxf(accS[na][2], accS[na][3]));
        }
        mx0 = fmaxf(mx0, __shfl_xor_sync(0xffffffffu, mx0, 1));
        mx0 = fmaxf(mx0, __shfl_xor_sync(0xffffffffu, mx0, 2));
        mx1 = fmaxf(mx1, __shfl_xor_sync(0xffffffffu, mx1, 1));
        mx1 = fmaxf(mx1, __shfl_xor_sync(0xffffffffu, mx1, 2));
        if ((lane & 3) == 0) {
            wmaxs[wN * 64 + r0]     = mx0;
            wmaxs[wN * 64 + r0 + 8] = mx1;
        }
        __syncthreads();
        float mn0 = fmaxf(m0, fmaxf(wmaxs[r0], wmaxs[64 + r0]));
        float mn1 = fmaxf(m1, fmaxf(wmaxs[r0 + 8], wmaxs[64 + r0 + 8]));
        float a0, a1;
        EX2F(a0, m0 - mn0);
        EX2F(a1, m1 - mn1);
        float s0 = 0.0f, s1 = 0.0f;
#pragma unroll
        for (int na = 0; na < 4; na++) {
            float p00, p01, p10, p11;
            EX2F(p00, accS[na][0] - mn0);
            EX2F(p01, accS[na][1] - mn0);
            EX2F(p10, accS[na][2] - mn1);
            EX2F(p11, accS[na][3] - mn1);
            __half hp00 = __float2half_rn(p00), hp01 = __float2half_rn(p01);
            __half hp10 = __float2half_rn(p10), hp11 = __float2half_rn(p11);
            s0 += __half2float(hp00) + __half2float(hp01);
            s1 += __half2float(hp10) + __half2float(hp11);
            int col = wN * 32 + na * 8 + 2 * lc;
            *(__half2*)(smc + PS_B + r0 * 144 + col * 2)       = __halves2half2(hp00, hp01);
            *(__half2*)(smc + PS_B + (r0 + 8) * 144 + col * 2) = __halves2half2(hp10, hp11);
        }
        s0 += __shfl_xor_sync(0xffffffffu, s0, 1);
        s0 += __shfl_xor_sync(0xffffffffu, s0, 2);
        s1 += __shfl_xor_sync(0xffffffffu, s1, 1);
        s1 += __shfl_xor_sync(0xffffffffu, s1, 2);
        if ((lane & 3) == 0) {
            wsums[wN * 64 + r0]     = s0;
            wsums[wN * 64 + r0 + 8] = s1;
        }
        if (nt < mt) { CP_WAIT1(); } else { CP_WAIT0(); }
        __syncthreads();
        l0 = l0 * a0 + wsums[r0] + wsums[64 + r0];
        l1 = l1 * a1 + wsums[r0 + 8] + wsums[64 + r0 + 8];
        m0 = mn0; m1 = mn1;
#pragma unroll
        for (int i = 0; i < 16; i++) {
            O[i][0] *= a0; O[i][1] *= a0; O[i][2] *= a1; O[i][3] *= a1;
        }

#pragma unroll 2
        for (int ks = 0; ks < 4; ks++) {
            uint32_t pf[4];
            LDMX4(pf, ps_base + ks * 32u);
#pragma unroll
            for (int pr = 0; pr < 8; pr++) {
                uint32_t vb[4];
                LDMX4(vb, vt_base + (uint32_t)(pr * 16 * 144) + ks * 32u);
                mma_f16(O[pr * 2],     pf, vb[0], vb[2]);
                mma_f16(O[pr * 2 + 1], pf, vb[1], vb[3]);
            }
        }
    }

    float i0, i1;
    asm("rcp.approx.f32 %0, %1;" : "=f"(i0) : "f"(l0));
    asm("rcp.approx.f32 %0, %1;" : "=f"(i1) : "f"(l1));
    int tg0 = mt * 64 + r0;
#pragma unroll
    for (int na = 0; na < 16; na++) {
        int col = wN * 128 + na * 8 + 2 * lc;
        *(float2*)(Yg + (size_t)tg0 * 256 + col)       = make_float2(O[na][0] * i0, O[na][1] * i0);
        *(float2*)(Yg + (size_t)(tg0 + 8) * 256 + col) = make_float2(O[na][2] * i1, O[na][3] * i1);
    }
}

// ---------------- combine ----------------
__global__ void combine_kernel(float* __restrict__ out) {
    int t = blockIdx.x, hp = blockIdx.y, b = blockIdx.z;
    int e = threadIdx.x;
    size_t y1i = ((size_t)(b * NH + 2 * hp)     * T_ + t) * 256 + e;
    size_t y2i = ((size_t)(b * NH + 2 * hp + 1) * T_ + t) * 256 + e;
    float y1 = g_Y[y1i], y2 = g_Y[y2i];
    float lam = g_lam[hp];
    float gv = g_C[((size_t)(b * T_ + t)) * CN + QKV_N + hp * 256 + e];
    float sg = gv / (1.0f + expf(-gv));
    float yv = (y1 - lam * y2) * sg;

    __shared__ float red[8];
    float s = yv * yv;
#pragma unroll
    for (int off = 16; off > 0; off >>= 1)
        s += __shfl_xor_sync(0xffffffffu, s, off);
    if ((e & 31) == 0) red[e >> 5] = s;
    __syncthreads();
    float tot = 0.0f;
#pragma unroll
    for (int w = 0; w < 8; w++) tot += red[w];
    float r = rsqrtf(tot * (1.0f / 256.0f) + 1e-6f) * ONE_MINUS_LI;
    out[((size_t)(b * T_ + t)) * DM + hp * 256 + e] = yv * r;
}

// ---------------- launch ----------------
extern "C" void kernel_launch(void* const* d_in, const int* in_sizes, int n_in,
                              void* d_out, int out_size) {
    const float* x    = (const float*)d_in[0];
    const float* Wqkv = (const float*)d_in[1];
    const float* lq1  = (const float*)d_in[2];
    const float* lk1  = (const float*)d_in[3];
    const float* lq2  = (const float*)d_in[4];
    const float* lk2  = (const float*)d_in[5];
    const float* Wg   = (const float*)d_in[6];
    float* out = (float*)d_out;

    float *c_p;
    __half *xhi_p, *xlo_p, *wt_p;
    cudaGetSymbolAddress((void**)&c_p,   g_C);
    cudaGetSymbolAddress((void**)&xhi_p, g_Xhi);
    cudaGetSymbolAddress((void**)&xlo_p, g_Xlo);
    cudaGetSymbolAddress((void**)&wt_p,  g_WT);

    rope_tab_kernel<<<T_, 64>>>();
    int nx4 = B_ * T_ * DM / 4;
    splitx_f16_kernel<<<(nx4 + 255) / 256, 256>>>(x, xhi_p, xlo_p, nx4);
    wt_f16_kernel<<<dim3(QKV_N / 32, DM / 32), dim3(32, 8)>>>(Wqkv, wt_p, DM, QKV_N, 0);
    wt_f16_kernel<<<dim3(DM / 32,    DM / 32), dim3(32, 8)>>>(Wg,   wt_p, DM, DM, QKV_N);

    cudaFuncSetAttribute(gemm_f16_kernel, cudaFuncAttributeMaxDynamicSharedMemorySize, GEMM_SMEM);
    gemm_f16_kernel<<<dim3(CN / GBN, (B_ * T_) / GBM), 256, GEMM_SMEM>>>(xhi_p, xlo_p, wt_p, c_p, CN, DM);

    lam_kernel<<<1, dim3(32, 8)>>>(lq1, lk1, lq2, lk2);
    cudaFuncSetAttribute(attn_kernel, cudaFuncAttributeMaxDynamicSharedMemorySize, ATT_SMEM);
    attn_kernel<<<dim3(T_ / 64, NH, B_), 256, ATT_SMEM>>>();
    combine_kernel<<<dim3(T_, HP_, B_), 256>>>(out);
}